// round 2
// baseline (speedup 1.0000x reference)
#include <cuda_runtime.h>
#include <math.h>

#define NP 2048
#define NC 64
#define CC 128
#define DD 64
#define XTOT (NP*NC*CC)

// ---------------- scratch (device globals; no allocation allowed) ----------
__device__ float g_Rf[NP*NP];        // row-normalized prior
__device__ float g_attn[NP*NP];      // logits -> attn (in place)
__device__ float g_Xf[2][XTOT];      // ping-pong forward path
__device__ float g_Xa[2][XTOT];      // ping-pong adaptive path
__device__ float g_res[XTOT];        // residual accumulator
__device__ float g_pooled[NP*CC];
__device__ float g_e1[NP*DD];
__device__ float g_e3[NP*DD];
__device__ float g_t[NP*DD];

// ---------------- block reduction helpers ----------------------------------
__device__ __forceinline__ float blockReduceSum(float v, float* red) {
    int lane = threadIdx.x & 31, wid = threadIdx.x >> 5;
    #pragma unroll
    for (int o = 16; o; o >>= 1) v += __shfl_xor_sync(0xffffffffu, v, o);
    if (lane == 0) red[wid] = v;
    __syncthreads();
    int nw = (blockDim.x + 31) >> 5;
    float r = (wid == 0 && lane < nw) ? red[lane] : 0.f;
    if (wid == 0) {
        #pragma unroll
        for (int o = 16; o; o >>= 1) r += __shfl_xor_sync(0xffffffffu, r, o);
        if (lane == 0) red[0] = r;
    }
    __syncthreads();
    r = red[0];
    __syncthreads();
    return r;
}

__device__ __forceinline__ float blockReduceMax(float v, float* red) {
    int lane = threadIdx.x & 31, wid = threadIdx.x >> 5;
    #pragma unroll
    for (int o = 16; o; o >>= 1) v = fmaxf(v, __shfl_xor_sync(0xffffffffu, v, o));
    if (lane == 0) red[wid] = v;
    __syncthreads();
    int nw = (blockDim.x + 31) >> 5;
    float r = (wid == 0 && lane < nw) ? red[lane] : -INFINITY;
    if (wid == 0) {
        #pragma unroll
        for (int o = 16; o; o >>= 1) r = fmaxf(r, __shfl_xor_sync(0xffffffffu, r, o));
        if (lane == 0) red[0] = r;
    }
    __syncthreads();
    r = red[0];
    __syncthreads();
    return r;
}

// ---------------- row-normalize prior ---------------------------------------
__global__ void rownorm_kernel(const float* __restrict__ prior, float* __restrict__ Rf) {
    __shared__ float red[32];
    int i = blockIdx.x;
    int t = threadIdx.x;                       // 256 threads
    const float* row = prior + i * NP;
    float s = 0.f;
    for (int j = t; j < NP; j += 256) s += row[j];
    s = blockReduceSum(s, red);
    float inv = 1.f / fmaxf(s, 1e-12f);
    float* orow = Rf + i * NP;
    for (int j = t; j < NP; j += 256) orow[j] = row[j] * inv;
}

// ---------------- protein-axis mean pool ------------------------------------
__global__ void pool_kernel(const float* __restrict__ Xa, float* __restrict__ pooled) {
    int i = blockIdx.x;
    int c = threadIdx.x;                       // 128 threads
    const float* base = Xa + i * (NC * CC) + c;
    float s = 0.f;
    #pragma unroll
    for (int k = 0; k < NC; k++) s += base[k * CC];
    pooled[i * CC + c] = s * (1.f / NC);
}

// ---------------- small naive NT gemm: C[m,n] = sum_k A[m,k]*B[n,k] --------
__global__ void small_nt_kernel(const float* __restrict__ A, const float* __restrict__ B,
                                float* __restrict__ C, int M, int N, int K) {
    int idx = blockIdx.x * blockDim.x + threadIdx.x;
    if (idx >= M * N) return;
    int m = idx / N, n = idx % N;
    const float* a = A + m * K;
    const float* b = B + n * K;
    float s = 0.f;
    for (int k = 0; k < K; k++) s += a[k] * b[k];
    C[idx] = s;
}

// ---------------- tiled SGEMM NN: C = A(MxK) * B(KxN), all row-major --------
__global__ void __launch_bounds__(256) sgemm_nn(const float* __restrict__ A,
                                                const float* __restrict__ B,
                                                float* __restrict__ C,
                                                int M, int N, int K) {
    __shared__ __align__(16) float As[8][128];
    __shared__ __align__(16) float Bs[8][128];
    int tid = threadIdx.x;
    int bm = blockIdx.y * 128, bn = blockIdx.x * 128;
    int tr = (tid >> 4) << 3;     // 0..120 step 8
    int tc = (tid & 15) << 3;
    int aRow = tid >> 1, aCol = (tid & 1) << 2;
    int bRow = tid >> 5, bCol = (tid & 31) << 2;
    const float* Ap = A + (bm + aRow) * K + aCol;
    const float* Bp = B + bRow * N + bn + bCol;

    float acc[8][8];
    #pragma unroll
    for (int i = 0; i < 8; i++)
        #pragma unroll
        for (int j = 0; j < 8; j++) acc[i][j] = 0.f;

    for (int k0 = 0; k0 < K; k0 += 8) {
        float4 av = *(const float4*)(Ap + k0);
        As[aCol + 0][aRow] = av.x; As[aCol + 1][aRow] = av.y;
        As[aCol + 2][aRow] = av.z; As[aCol + 3][aRow] = av.w;
        float4 bv = *(const float4*)(Bp + k0 * N);
        *(float4*)&Bs[bRow][bCol] = bv;
        __syncthreads();
        #pragma unroll
        for (int kk = 0; kk < 8; kk++) {
            float4 a0 = *(const float4*)&As[kk][tr];
            float4 a1 = *(const float4*)&As[kk][tr + 4];
            float4 b0 = *(const float4*)&Bs[kk][tc];
            float4 b1 = *(const float4*)&Bs[kk][tc + 4];
            float ar[8] = {a0.x, a0.y, a0.z, a0.w, a1.x, a1.y, a1.z, a1.w};
            float br[8] = {b0.x, b0.y, b0.z, b0.w, b1.x, b1.y, b1.z, b1.w};
            #pragma unroll
            for (int i = 0; i < 8; i++)
                #pragma unroll
                for (int j = 0; j < 8; j++) acc[i][j] = fmaf(ar[i], br[j], acc[i][j]);
        }
        __syncthreads();
    }
    #pragma unroll
    for (int i = 0; i < 8; i++) {
        float* crow = C + (bm + tr + i) * N + bn + tc;
        *(float4*)(crow)     = make_float4(acc[i][0], acc[i][1], acc[i][2], acc[i][3]);
        *(float4*)(crow + 4) = make_float4(acc[i][4], acc[i][5], acc[i][6], acc[i][7]);
    }
}

// ---------------- tiled SGEMM NT: C[m,n] (+)= sum_k A[m,k]*B[n,k] ----------
__global__ void __launch_bounds__(256) sgemm_nt(const float* __restrict__ A,
                                                const float* __restrict__ B,
                                                float* __restrict__ C,
                                                int M, int N, int K, int accumulate) {
    __shared__ __align__(16) float As[8][128];
    __shared__ __align__(16) float Bs[8][128];
    int tid = threadIdx.x;
    int bm = blockIdx.y * 128, bn = blockIdx.x * 128;
    int tr = (tid >> 4) << 3;
    int tc = (tid & 15) << 3;
    int aRow = tid >> 1, aCol = (tid & 1) << 2;
    int bN = tid >> 1, bK = (tid & 1) << 2;
    const float* Ap = A + (bm + aRow) * K + aCol;
    const float* Bp = B + (bn + bN) * K + bK;

    float acc[8][8];
    #pragma unroll
    for (int i = 0; i < 8; i++)
        #pragma unroll
        for (int j = 0; j < 8; j++) acc[i][j] = 0.f;

    for (int k0 = 0; k0 < K; k0 += 8) {
        float4 av = *(const float4*)(Ap + k0);
        As[aCol + 0][aRow] = av.x; As[aCol + 1][aRow] = av.y;
        As[aCol + 2][aRow] = av.z; As[aCol + 3][aRow] = av.w;
        float4 bv = *(const float4*)(Bp + k0);
        Bs[bK + 0][bN] = bv.x; Bs[bK + 1][bN] = bv.y;
        Bs[bK + 2][bN] = bv.z; Bs[bK + 3][bN] = bv.w;
        __syncthreads();
        #pragma unroll
        for (int kk = 0; kk < 8; kk++) {
            float4 a0 = *(const float4*)&As[kk][tr];
            float4 a1 = *(const float4*)&As[kk][tr + 4];
            float4 b0 = *(const float4*)&Bs[kk][tc];
            float4 b1 = *(const float4*)&Bs[kk][tc + 4];
            float ar[8] = {a0.x, a0.y, a0.z, a0.w, a1.x, a1.y, a1.z, a1.w};
            float br[8] = {b0.x, b0.y, b0.z, b0.w, b1.x, b1.y, b1.z, b1.w};
            #pragma unroll
            for (int i = 0; i < 8; i++)
                #pragma unroll
                for (int j = 0; j < 8; j++) acc[i][j] = fmaf(ar[i], br[j], acc[i][j]);
        }
        __syncthreads();
    }
    #pragma unroll
    for (int i = 0; i < 8; i++) {
        float* crow = C + (bm + tr + i) * N + bn + tc;
        if (accumulate) {
            float4 c0 = *(float4*)(crow);
            float4 c1 = *(float4*)(crow + 4);
            *(float4*)(crow)     = make_float4(c0.x + acc[i][0], c0.y + acc[i][1],
                                               c0.z + acc[i][2], c0.w + acc[i][3]);
            *(float4*)(crow + 4) = make_float4(c1.x + acc[i][4], c1.y + acc[i][5],
                                               c1.z + acc[i][6], c1.w + acc[i][7]);
        } else {
            *(float4*)(crow)     = make_float4(acc[i][0], acc[i][1], acc[i][2], acc[i][3]);
            *(float4*)(crow + 4) = make_float4(acc[i][4], acc[i][5], acc[i][6], acc[i][7]);
        }
    }
}

// ---------------- softmax + top-p sparsify + renorm (one block per row) -----
__global__ void __launch_bounds__(512) topp_kernel(float* __restrict__ attn) {
    const float P = 0.9f;
    __shared__ float a[NP];   // normalized attn values
    __shared__ float s[NP];   // sorted copy (descending)
    __shared__ float cs[512]; // chunk prefix
    __shared__ float red[32];
    __shared__ float sh_thr;

    int t = threadIdx.x;      // 512 threads, 4 elems each
    float* row = attn + blockIdx.x * NP;

    // softmax
    float v[4], mx = -INFINITY;
    #pragma unroll
    for (int e = 0; e < 4; e++) { v[e] = row[t + e * 512]; mx = fmaxf(mx, v[e]); }
    mx = blockReduceMax(mx, red);
    float z = 0.f;
    #pragma unroll
    for (int e = 0; e < 4; e++) { float ex = expf(v[e] - mx); a[t + e * 512] = ex; z += ex; }
    z = blockReduceSum(z, red);
    float invZ = 1.f / z;
    #pragma unroll
    for (int e = 0; e < 4; e++) { a[t + e * 512] *= invZ; s[t + e * 512] = a[t + e * 512]; }
    __syncthreads();

    // bitonic sort descending (2048 elems, 512 threads)
    for (unsigned k = 2; k <= NP; k <<= 1) {
        for (unsigned j = k >> 1; j > 0; j >>= 1) {
            #pragma unroll
            for (int e = 0; e < 4; e++) {
                unsigned i = t + e * 512;
                unsigned l = i ^ j;
                if (l > i) {
                    float si = s[i], sl = s[l];
                    bool descRegion = ((i & k) == 0);
                    if (descRegion ? (si < sl) : (si > sl)) { s[i] = sl; s[l] = si; }
                }
            }
            __syncthreads();
        }
    }

    // per-thread chunk of 4 contiguous sorted values
    float c0 = s[4 * t] + s[4 * t + 1] + s[4 * t + 2] + s[4 * t + 3];
    cs[t] = c0;
    __syncthreads();
    // Hillis-Steele inclusive scan over 512 chunk sums
    for (int off = 1; off < 512; off <<= 1) {
        float mine = cs[t];
        float add = (t >= off) ? cs[t - off] : 0.f;
        __syncthreads();
        cs[t] = mine + add;
        __syncthreads();
    }
    float base = cs[t] - c0;  // exclusive prefix of my chunk

    // m = count of inclusive prefixes < P; thr = s[m]
    float run = base;
    int cnt = 0;
    #pragma unroll
    for (int e = 0; e < 4; e++) { run += s[4 * t + e]; if (run < P) cnt++; }
    float cntf = blockReduceSum((float)cnt, red);
    if (t == 0) {
        int m = (int)(cntf + 0.5f);
        if (m > NP - 1) m = NP - 1;
        sh_thr = s[m];
    }
    __syncthreads();
    float thr = sh_thr;

    // mask + renorm
    float msum = 0.f;
    float mv[4];
    #pragma unroll
    for (int e = 0; e < 4; e++) {
        float av = a[t + e * 512];
        mv[e] = (av >= thr) ? av : 0.f;
        msum += mv[e];
    }
    msum = blockReduceSum(msum, red);
    float inv = 1.f / fmaxf(msum, 1e-12f);
    #pragma unroll
    for (int e = 0; e < 4; e++) row[t + e * 512] = mv[e] * inv;
}

// ---------------- fused gate + residual + layernorm -------------------------
__global__ void __launch_bounds__(128) ln_kernel(const float* __restrict__ x,
                                                 const float* __restrict__ res,
                                                 const float* __restrict__ gamma,
                                                 const float* __restrict__ beta,
                                                 const float* __restrict__ alpha,
                                                 float* __restrict__ out) {
    __shared__ float red[32];
    int row = blockIdx.x;
    int c = threadIdx.x;  // 128 threads
    float gate = 1.f / (1.f + expf(-alpha[0]));
    int idx = row * CC + c;
    float h = x[idx] + gate * res[idx];
    float mu = blockReduceSum(h, red) * (1.f / CC);
    float d = h - mu;
    float var = blockReduceSum(d * d, red) * (1.f / CC);
    out[idx] = d * rsqrtf(var + 1e-5f) * gamma[c] + beta[c];
}

// ---------------- launch ----------------------------------------------------
extern "C" void kernel_launch(void* const* d_in, const int* in_sizes, int n_in,
                              void* d_out, int out_size) {
    const float* x     = (const float*)d_in[0];   // (2048,64,128)
    const float* prior = (const float*)d_in[1];   // (2048,2048)
    const float* W1    = (const float*)d_in[2];   // (64,128)
    const float* W2    = (const float*)d_in[3];   // (64,64)
    const float* W3    = (const float*)d_in[4];   // (64,128)
    const float* pfw   = (const float*)d_in[5];   // (2,128,128)
    const float* adw   = (const float*)d_in[6];   // (2,128,128)
    const float* gamma = (const float*)d_in[7];   // (128,)
    const float* beta  = (const float*)d_in[8];   // (128,)
    const float* alpha = (const float*)d_in[9];   // (1,)
    float* out = (float*)d_out;

    float *Rf, *attn, *xf0, *xf1, *xa0, *xa1, *res, *pooled, *e1, *e3, *tt;
    cudaGetSymbolAddress((void**)&Rf, g_Rf);
    cudaGetSymbolAddress((void**)&attn, g_attn);
    cudaGetSymbolAddress((void**)&xf0, g_Xf);
    cudaGetSymbolAddress((void**)&xa0, g_Xa);
    cudaGetSymbolAddress((void**)&res, g_res);
    cudaGetSymbolAddress((void**)&pooled, g_pooled);
    cudaGetSymbolAddress((void**)&e1, g_e1);
    cudaGetSymbolAddress((void**)&e3, g_e3);
    cudaGetSymbolAddress((void**)&tt, g_t);
    xf1 = xf0 + XTOT;
    xa1 = xa0 + XTOT;

    rownorm_kernel<<<NP, 256>>>(prior, Rf);

    const float* Xf_cur = x;
    const float* Xa_cur = x;

    for (int step = 0; step < 2; step++) {
        pool_kernel<<<NP, 128>>>(Xa_cur, pooled);
        small_nt_kernel<<<(NP * DD) / 256, 256>>>(pooled, W1, e1, NP, DD, CC);
        small_nt_kernel<<<(NP * DD) / 256, 256>>>(pooled, W3, e3, NP, DD, CC);
        small_nt_kernel<<<(NP * DD) / 256, 256>>>(e1, W2, tt, NP, DD, DD);
        // logits = t @ e3^T  (TAU = 1)
        sgemm_nt<<<dim3(NP / 128, NP / 128), 256>>>(tt, e3, attn, NP, NP, DD, 0);
        topp_kernel<<<NP, 512>>>(attn);

        float* xfn = step ? xf1 : xf0;
        float* xan = step ? xa1 : xa0;
        // Xf = Rf @ Xf ; Xa = attn @ Xa   (B viewed as 2048 x 8192)
        sgemm_nn<<<dim3((NC * CC) / 128, NP / 128), 256>>>(Rf, Xf_cur, xfn, NP, NC * CC, NP);
        sgemm_nn<<<dim3((NC * CC) / 128, NP / 128), 256>>>(attn, Xa_cur, xan, NP, NC * CC, NP);
        // residual += Xf@pfw^T + Xa@adw^T  (rows = 131072, N=K=128)
        sgemm_nt<<<dim3(1, (NP * NC) / 128), 256>>>(xfn, pfw + step * CC * CC, res,
                                                    NP * NC, CC, CC, step > 0 ? 1 : 0);
        sgemm_nt<<<dim3(1, (NP * NC) / 128), 256>>>(xan, adw + step * CC * CC, res,
                                                    NP * NC, CC, CC, 1);
        Xf_cur = xfn;
        Xa_cur = xan;
    }

    ln_kernel<<<NP * NC, 128>>>(x, res, gamma, beta, alpha, out);
}

// round 6
// speedup vs baseline: 2.9294x; 2.9294x over previous
#include <cuda_runtime.h>
#include <cuda_bf16.h>
#include <math.h>
#include <stdint.h>

#define NP 2048
#define NC 64
#define CC 128
#define DD 64
#define NOUT (NC*CC)          // 8192
#define XTOT (NP*NOUT)

// ================= scratch (device globals; no allocation allowed) =========
__device__ __align__(16) float g_Rf[NP*NP];
__device__ __align__(16) float g_attn[NP*NP];
__device__ __align__(16) float g_Xf[XTOT];
__device__ __align__(16) float g_Xa[XTOT];
__device__ __align__(16) float g_res[XTOT];
__device__ __align__(16) float g_pooled[NP*CC];
__device__ __align__(16) float g_e3[NP*DD];
__device__ __align__(16) float g_t[NP*DD];
__device__ __align__(16) float g_W21[DD*CC];
__device__ __align__(16) __nv_bfloat16 g_RfH[NP*NP];
__device__ __align__(16) __nv_bfloat16 g_RfL[NP*NP];
__device__ __align__(16) __nv_bfloat16 g_AtH[NP*NP];
__device__ __align__(16) __nv_bfloat16 g_AtL[NP*NP];
__device__ __align__(16) __nv_bfloat16 g_Bh[XTOT];
__device__ __align__(16) __nv_bfloat16 g_Bl[XTOT];

// ================= PTX helpers (all sm_80-era; valid on plain sm_103) ======
__device__ __forceinline__ uint32_t smem_to_u32(const void* p) {
    uint32_t a;
    asm("{ .reg .u64 t; cvta.to.shared.u64 t, %1; cvt.u32.u64 %0, t; }" : "=r"(a) : "l"(p));
    return a;
}
__device__ __forceinline__ void cp16(uint32_t saddr, const void* g) {
    asm volatile("cp.async.cg.shared.global [%0], [%1], 16;" :: "r"(saddr), "l"(g) : "memory");
}
__device__ __forceinline__ void ldsm_x4(uint32_t* r, uint32_t addr) {
    asm volatile("ldmatrix.sync.aligned.m8n8.x4.shared.b16 {%0,%1,%2,%3}, [%4];"
        : "=r"(r[0]), "=r"(r[1]), "=r"(r[2]), "=r"(r[3]) : "r"(addr));
}
__device__ __forceinline__ void ldsm_x4_t(uint32_t* r, uint32_t addr) {
    asm volatile("ldmatrix.sync.aligned.m8n8.x4.trans.shared.b16 {%0,%1,%2,%3}, [%4];"
        : "=r"(r[0]), "=r"(r[1]), "=r"(r[2]), "=r"(r[3]) : "r"(addr));
}
__device__ __forceinline__ void mma_bf16(float* d, const uint32_t* a, uint32_t b0, uint32_t b1) {
    asm volatile(
        "mma.sync.aligned.m16n8k16.row.col.f32.bf16.bf16.f32 "
        "{%0,%1,%2,%3}, {%4,%5,%6,%7}, {%8,%9}, {%0,%1,%2,%3};"
        : "+f"(d[0]), "+f"(d[1]), "+f"(d[2]), "+f"(d[3])
        : "r"(a[0]), "r"(a[1]), "r"(a[2]), "r"(a[3]), "r"(b0), "r"(b1));
}

// ================= reductions ==============================================
__device__ __forceinline__ float blockReduceSum(float v, float* red) {
    int lane = threadIdx.x & 31, wid = threadIdx.x >> 5;
    #pragma unroll
    for (int o = 16; o; o >>= 1) v += __shfl_xor_sync(0xffffffffu, v, o);
    if (lane == 0) red[wid] = v;
    __syncthreads();
    int nw = (blockDim.x + 31) >> 5;
    float r = (wid == 0 && lane < nw) ? red[lane] : 0.f;
    if (wid == 0) {
        #pragma unroll
        for (int o = 16; o; o >>= 1) r += __shfl_xor_sync(0xffffffffu, r, o);
        if (lane == 0) red[0] = r;
    }
    __syncthreads();
    r = red[0];
    __syncthreads();
    return r;
}
__device__ __forceinline__ float blockReduceMax(float v, float* red) {
    int lane = threadIdx.x & 31, wid = threadIdx.x >> 5;
    #pragma unroll
    for (int o = 16; o; o >>= 1) v = fmaxf(v, __shfl_xor_sync(0xffffffffu, v, o));
    if (lane == 0) red[wid] = v;
    __syncthreads();
    int nw = (blockDim.x + 31) >> 5;
    float r = (wid == 0 && lane < nw) ? red[lane] : -INFINITY;
    if (wid == 0) {
        #pragma unroll
        for (int o = 16; o; o >>= 1) r = fmaxf(r, __shfl_xor_sync(0xffffffffu, r, o));
        if (lane == 0) red[0] = r;
    }
    __syncthreads();
    r = red[0];
    __syncthreads();
    return r;
}

// ================= small kernels ===========================================
__global__ void rownorm_kernel(const float* __restrict__ prior, float* __restrict__ Rf) {
    __shared__ float red[32];
    int i = blockIdx.x, t = threadIdx.x;
    const float* row = prior + (size_t)i * NP;
    float s = 0.f;
    for (int j = t; j < NP; j += 256) s += row[j];
    s = blockReduceSum(s, red);
    float inv = 1.f / fmaxf(s, 1e-12f);
    float* orow = Rf + (size_t)i * NP;
    for (int j = t; j < NP; j += 256) orow[j] = row[j] * inv;
}

__global__ void pool_kernel(const float* __restrict__ Xa, float* __restrict__ pooled) {
    int i = blockIdx.x, c = threadIdx.x;  // 128 threads
    const float* base = Xa + (size_t)i * (NC * CC) + c;
    float s = 0.f;
    #pragma unroll
    for (int k = 0; k < NC; k++) s += base[k * CC];
    pooled[i * CC + c] = s * (1.f / NC);
}

// W21 = W2 @ W1  : (64 x 128), K=64
__global__ void w21_kernel(const float* __restrict__ W2, const float* __restrict__ W1,
                           float* __restrict__ W21) {
    int idx = blockIdx.x * 256 + threadIdx.x;   // 8192 total
    int d = idx >> 7, c = idx & 127;
    float s = 0.f;
    for (int e = 0; e < DD; e++) s += W2[d * DD + e] * W1[e * CC + c];
    W21[idx] = s;
}

// t = pooled @ W21^T ; e3 = pooled @ W3^T   (2048 x 64, K=128)
__global__ void __launch_bounds__(256) proj_kernel(const float* __restrict__ pooled,
                                                   const float* __restrict__ W21,
                                                   const float* __restrict__ W3,
                                                   float* __restrict__ t_out,
                                                   float* __restrict__ e3_out) {
    __shared__ float sp[16][CC];
    int row0 = blockIdx.x * 16;
    int tid = threadIdx.x;
    for (int i = tid; i < 16 * CC; i += 256)
        sp[i >> 7][i & 127] = pooled[(size_t)(row0 + (i >> 7)) * CC + (i & 127)];
    __syncthreads();
    int n = tid & 63, rq = tid >> 6;
    float at[4] = {0, 0, 0, 0}, ae[4] = {0, 0, 0, 0};
    for (int c = 0; c < CC; c++) {
        float w21 = __ldg(&W21[n * CC + c]);
        float w3  = __ldg(&W3[n * CC + c]);
        #pragma unroll
        for (int j = 0; j < 4; j++) {
            float p = sp[rq + 4 * j][c];
            at[j] = fmaf(p, w21, at[j]);
            ae[j] = fmaf(p, w3, ae[j]);
        }
    }
    #pragma unroll
    for (int j = 0; j < 4; j++) {
        int r = row0 + rq + 4 * j;
        t_out[r * DD + n] = at[j];
        e3_out[r * DD + n] = ae[j];
    }
}

// fp32 -> (hi, lo) bf16, same layout. Grid sized by caller: count/1024 blocks.
__global__ void conv_kernel(const float* __restrict__ A,
                            __nv_bfloat16* __restrict__ H, __nv_bfloat16* __restrict__ L) {
    size_t i = (size_t)(blockIdx.x * 256 + threadIdx.x) * 4;
    float4 v = *(const float4*)(A + i);
    __nv_bfloat16 h0 = __float2bfloat16_rn(v.x), h1 = __float2bfloat16_rn(v.y);
    __nv_bfloat16 h2 = __float2bfloat16_rn(v.z), h3 = __float2bfloat16_rn(v.w);
    __nv_bfloat162 hh0; hh0.x = h0; hh0.y = h1;
    __nv_bfloat162 hh1; hh1.x = h2; hh1.y = h3;
    __nv_bfloat162 ll0, ll1;
    ll0.x = __float2bfloat16_rn(v.x - __bfloat162float(h0));
    ll0.y = __float2bfloat16_rn(v.y - __bfloat162float(h1));
    ll1.x = __float2bfloat16_rn(v.z - __bfloat162float(h2));
    ll1.y = __float2bfloat16_rn(v.w - __bfloat162float(h3));
    *(__nv_bfloat162*)(H + i) = hh0; *(__nv_bfloat162*)(H + i + 2) = hh1;
    *(__nv_bfloat162*)(L + i) = ll0; *(__nv_bfloat162*)(L + i + 2) = ll1;
}

// ================= split-bf16 HMMA GEMM ====================================
// C[2048 x 8192] = A[2048 x 2048] @ B[2048 x 8192].
// A hi/lo bf16 row-major (K contiguous); B hi/lo bf16 row-major (N contiguous).
// CTA tile 128x128, K-chunk 64, double-buffered cp.async.
// smem buffer layout (64KB each, 2 buffers):
//   Ah @ 0      (128 rows x 128B, swizzle: off ^ (((off>>7)&7)<<4))
//   Al @ 16384
//   Bh @ 32768  (64 k-rows x 256B, swizzle: off ^ (((off>>8)&7)<<4))
//   Bl @ 49152
#define GEMM_SMEM (2 * 65536)

__global__ void __launch_bounds__(256, 1) mma_gemm(
    const __nv_bfloat16* __restrict__ Ah, const __nv_bfloat16* __restrict__ Al,
    const __nv_bfloat16* __restrict__ Bh, const __nv_bfloat16* __restrict__ Bl,
    float* __restrict__ C) {
    extern __shared__ char smem[];
    uint32_t sbase = smem_to_u32(smem);
    int tid = threadIdx.x, wid = tid >> 5, lane = tid & 31;
    int bm = blockIdx.y * 128, bn = blockIdx.x * 128;
    int wm = (wid >> 1) * 32;   // warp m offset within tile (4 warps)
    int wn = (wid & 1) * 64;    // warp n offset within tile (2 warps)

    float acc[2][8][4];
    #pragma unroll
    for (int i = 0; i < 2; i++)
        #pragma unroll
        for (int j = 0; j < 8; j++)
            #pragma unroll
            for (int q = 0; q < 4; q++) acc[i][j][q] = 0.f;

    const int NCHUNK = NP / 64;   // 32

    // ---- async load of one K-chunk into buffer `buf` ----
    auto load_chunk = [&](int ch, int buf) {
        int k0 = ch * 64;
        uint32_t s = sbase + buf * 65536;
        // A hi/lo: 1024 chunks of 16B each (128 rows x 8 chunks)
        #pragma unroll
        for (int t = 0; t < 4; t++) {
            int i = tid + t * 256;
            int r = i >> 3, c = i & 7;
            uint32_t off = r * 128 + c * 16;
            uint32_t sw = off ^ (((off >> 7) & 7) << 4);
            const char* gh = (const char*)(Ah + (size_t)(bm + r) * NP + k0) + c * 16;
            const char* gl = (const char*)(Al + (size_t)(bm + r) * NP + k0) + c * 16;
            cp16(s + sw, gh);
            cp16(s + 16384 + sw, gl);
        }
        // B hi/lo: 1024 chunks (64 k-rows x 16 chunks)
        #pragma unroll
        for (int t = 0; t < 4; t++) {
            int i = tid + t * 256;
            int k = i >> 4, n = i & 15;
            uint32_t off = k * 256 + n * 16;
            uint32_t sw = off ^ (((off >> 8) & 7) << 4);
            const char* gh = (const char*)(Bh + (size_t)(k0 + k) * NOUT + bn) + n * 16;
            const char* gl = (const char*)(Bl + (size_t)(k0 + k) * NOUT + bn) + n * 16;
            cp16(s + 32768 + sw, gh);
            cp16(s + 49152 + sw, gl);
        }
        asm volatile("cp.async.commit_group;" ::: "memory");
    };

    load_chunk(0, 0);

    for (int ch = 0; ch < NCHUNK; ch++) {
        if (ch + 1 < NCHUNK) load_chunk(ch + 1, (ch + 1) & 1);
        if (ch + 1 < NCHUNK) asm volatile("cp.async.wait_group 1;" ::: "memory");
        else                 asm volatile("cp.async.wait_group 0;" ::: "memory");
        __syncthreads();

        uint32_t s = sbase + (ch & 1) * 65536;
        uint32_t sAh = s, sAl = s + 16384, sBh = s + 32768, sBl = s + 49152;

        #pragma unroll
        for (int kk = 0; kk < 64; kk += 16) {
            uint32_t ah[2][4], al[2][4], bh[4][4], bl[4][4];
            // A fragments (row-major, non-trans)
            #pragma unroll
            for (int p = 0; p < 2; p++) {
                uint32_t off = (uint32_t)(wm + 16 * p + (lane & 15)) * 128
                             + kk * 2 + (lane >> 4) * 16;
                uint32_t sw = off ^ (((off >> 7) & 7) << 4);
                ldsm_x4(ah[p], sAh + sw);
                ldsm_x4(al[p], sAl + sw);
            }
            // B fragments (.trans from [k][n] layout)
            #pragma unroll
            for (int p = 0; p < 4; p++) {
                uint32_t off = (uint32_t)(kk + (lane & 15)) * 256
                             + (wn + p * 16) * 2 + (lane >> 4) * 16;
                uint32_t sw = off ^ (((off >> 8) & 7) << 4);
                ldsm_x4_t(bh[p], sBh + sw);
                ldsm_x4_t(bl[p], sBl + sw);
            }
            // hi*hi
            #pragma unroll
            for (int i = 0; i < 2; i++)
                #pragma unroll
                for (int j = 0; j < 8; j++)
                    mma_bf16(acc[i][j], ah[i], bh[j >> 1][(j & 1) * 2], bh[j >> 1][(j & 1) * 2 + 1]);
            // lo*hi
            #pragma unroll
            for (int i = 0; i < 2; i++)
                #pragma unroll
                for (int j = 0; j < 8; j++)
                    mma_bf16(acc[i][j], al[i], bh[j >> 1][(j & 1) * 2], bh[j >> 1][(j & 1) * 2 + 1]);
            // hi*lo
            #pragma unroll
            for (int i = 0; i < 2; i++)
                #pragma unroll
                for (int j = 0; j < 8; j++)
                    mma_bf16(acc[i][j], ah[i], bl[j >> 1][(j & 1) * 2], bl[j >> 1][(j & 1) * 2 + 1]);
        }
        __syncthreads();
    }

    // epilogue
    int grp = lane >> 2, tig = lane & 3;
    #pragma unroll
    for (int i = 0; i < 2; i++)
        #pragma unroll
        for (int j = 0; j < 8; j++) {
            int row = bm + wm + 16 * i + grp;
            int col = bn + wn + 8 * j + 2 * tig;
            *(float2*)(C + (size_t)row * NOUT + col) = make_float2(acc[i][j][0], acc[i][j][1]);
            *(float2*)(C + (size_t)(row + 8) * NOUT + col) = make_float2(acc[i][j][2], acc[i][j][3]);
        }
}

// ================= fp32 tiled NT (logits + delta) ==========================
__global__ void __launch_bounds__(256) sgemm_nt(const float* __restrict__ A,
                                                const float* __restrict__ B,
                                                float* __restrict__ C,
                                                int M, int N, int K, int accumulate) {
    __shared__ __align__(16) float As[8][128];
    __shared__ __align__(16) float Bs[8][128];
    int tid = threadIdx.x;
    int bm = blockIdx.y * 128, bn = blockIdx.x * 128;
    int tr = (tid >> 4) << 3;
    int tc = (tid & 15) << 3;
    int aRow = tid >> 1, aCol = (tid & 1) << 2;
    int bN = tid >> 1, bK = (tid & 1) << 2;
    const float* Ap = A + (size_t)(bm + aRow) * K + aCol;
    const float* Bp = B + (size_t)(bn + bN) * K + bK;
    float acc[8][8];
    #pragma unroll
    for (int i = 0; i < 8; i++)
        #pragma unroll
        for (int j = 0; j < 8; j++) acc[i][j] = 0.f;
    for (int k0 = 0; k0 < K; k0 += 8) {
        float4 av = *(const float4*)(Ap + k0);
        As[aCol + 0][aRow] = av.x; As[aCol + 1][aRow] = av.y;
        As[aCol + 2][aRow] = av.z; As[aCol + 3][aRow] = av.w;
        float4 bv = *(const float4*)(Bp + k0);
        Bs[bK + 0][bN] = bv.x; Bs[bK + 1][bN] = bv.y;
        Bs[bK + 2][bN] = bv.z; Bs[bK + 3][bN] = bv.w;
        __syncthreads();
        #pragma unroll
        for (int kk = 0; kk < 8; kk++) {
            float4 a0 = *(const float4*)&As[kk][tr];
            float4 a1 = *(const float4*)&As[kk][tr + 4];
            float4 b0 = *(const float4*)&Bs[kk][tc];
            float4 b1 = *(const float4*)&Bs[kk][tc + 4];
            float ar[8] = {a0.x, a0.y, a0.z, a0.w, a1.x, a1.y, a1.z, a1.w};
            float br[8] = {b0.x, b0.y, b0.z, b0.w, b1.x, b1.y, b1.z, b1.w};
            #pragma unroll
            for (int i = 0; i < 8; i++)
                #pragma unroll
                for (int j = 0; j < 8; j++) acc[i][j] = fmaf(ar[i], br[j], acc[i][j]);
        }
        __syncthreads();
    }
    #pragma unroll
    for (int i = 0; i < 8; i++) {
        float* crow = C + (size_t)(bm + tr + i) * N + bn + tc;
        if (accumulate) {
            float4 c0 = *(float4*)(crow);
            float4 c1 = *(float4*)(crow + 4);
            *(float4*)(crow)     = make_float4(c0.x + acc[i][0], c0.y + acc[i][1],
                                               c0.z + acc[i][2], c0.w + acc[i][3]);
            *(float4*)(crow + 4) = make_float4(c1.x + acc[i][4], c1.y + acc[i][5],
                                               c1.z + acc[i][6], c1.w + acc[i][7]);
        } else {
            *(float4*)(crow)     = make_float4(acc[i][0], acc[i][1], acc[i][2], acc[i][3]);
            *(float4*)(crow + 4) = make_float4(acc[i][4], acc[i][5], acc[i][6], acc[i][7]);
        }
    }
}

// ================= softmax + top-p =========================================
__global__ void __launch_bounds__(512) topp_kernel(float* __restrict__ attn) {
    const float P = 0.9f;
    __shared__ float a[NP];
    __shared__ float s[NP];
    __shared__ float cs[512];
    __shared__ float red[32];
    __shared__ float sh_thr;
    int t = threadIdx.x;
    float* row = attn + (size_t)blockIdx.x * NP;
    float v[4], mx = -INFINITY;
    #pragma unroll
    for (int e = 0; e < 4; e++) { v[e] = row[t + e * 512]; mx = fmaxf(mx, v[e]); }
    mx = blockReduceMax(mx, red);
    float z = 0.f;
    #pragma unroll
    for (int e = 0; e < 4; e++) { float ex = expf(v[e] - mx); a[t + e * 512] = ex; z += ex; }
    z = blockReduceSum(z, red);
    float invZ = 1.f / z;
    #pragma unroll
    for (int e = 0; e < 4; e++) { a[t + e * 512] *= invZ; s[t + e * 512] = a[t + e * 512]; }
    __syncthreads();
    for (unsigned k = 2; k <= NP; k <<= 1) {
        for (unsigned j = k >> 1; j > 0; j >>= 1) {
            #pragma unroll
            for (int e = 0; e < 4; e++) {
                unsigned i = t + e * 512;
                unsigned l = i ^ j;
                if (l > i) {
                    float si = s[i], sl = s[l];
                    bool descRegion = ((i & k) == 0);
                    if (descRegion ? (si < sl) : (si > sl)) { s[i] = sl; s[l] = si; }
                }
            }
            __syncthreads();
        }
    }
    float c0 = s[4 * t] + s[4 * t + 1] + s[4 * t + 2] + s[4 * t + 3];
    cs[t] = c0;
    __syncthreads();
    for (int off = 1; off < 512; off <<= 1) {
        float mine = cs[t];
        float add = (t >= off) ? cs[t - off] : 0.f;
        __syncthreads();
        cs[t] = mine + add;
        __syncthreads();
    }
    float base = cs[t] - c0;
    float run = base;
    int cnt = 0;
    #pragma unroll
    for (int e = 0; e < 4; e++) { run += s[4 * t + e]; if (run < P) cnt++; }
    float cntf = blockReduceSum((float)cnt, red);
    if (t == 0) {
        int m = (int)(cntf + 0.5f);
        if (m > NP - 1) m = NP - 1;
        sh_thr = s[m];
    }
    __syncthreads();
    float thr = sh_thr;
    float msum = 0.f, mv[4];
    #pragma unroll
    for (int e = 0; e < 4; e++) {
        float av = a[t + e * 512];
        mv[e] = (av >= thr) ? av : 0.f;
        msum += mv[e];
    }
    msum = blockReduceSum(msum, red);
    float inv = 1.f / fmaxf(msum, 1e-12f);
    #pragma unroll
    for (int e = 0; e < 4; e++) row[t + e * 512] = mv[e] * inv;
}

// ================= gate + residual + layernorm =============================
__global__ void __launch_bounds__(128) ln_kernel(const float* __restrict__ x,
                                                 const float* __restrict__ res,
                                                 const float* __restrict__ gamma,
                                                 const float* __restrict__ beta,
                                                 const float* __restrict__ alpha,
                                                 float* __restrict__ out) {
    __shared__ float red[32];
    int row = blockIdx.x, c = threadIdx.x;
    float gate = 1.f / (1.f + expf(-alpha[0]));
    size_t idx = (size_t)row * CC + c;
    float h = x[idx] + gate * res[idx];
    float mu = blockReduceSum(h, red) * (1.f / CC);
    float d = h - mu;
    float var = blockReduceSum(d * d, red) * (1.f / CC);
    out[idx] = d * rsqrtf(var + 1e-5f) * gamma[c] + beta[c];
}

// ================= launch ==================================================
extern "C" void kernel_launch(void* const* d_in, const int* in_sizes, int n_in,
                              void* d_out, int out_size) {
    const float* x     = (const float*)d_in[0];
    const float* prior = (const float*)d_in[1];
    const float* W1    = (const float*)d_in[2];
    const float* W2    = (const float*)d_in[3];
    const float* W3    = (const float*)d_in[4];
    const float* pfw   = (const float*)d_in[5];
    const float* adw   = (const float*)d_in[6];
    const float* gamma = (const float*)d_in[7];
    const float* beta  = (const float*)d_in[8];
    const float* alpha = (const float*)d_in[9];
    float* out = (float*)d_out;

    float *Rf, *attn, *xf, *xa, *res, *pooled, *e3, *tt, *W21;
    __nv_bfloat16 *RfH, *RfL, *AtH, *AtL, *Bh, *Bl;
    cudaGetSymbolAddress((void**)&Rf, g_Rf);
    cudaGetSymbolAddress((void**)&attn, g_attn);
    cudaGetSymbolAddress((void**)&xf, g_Xf);
    cudaGetSymbolAddress((void**)&xa, g_Xa);
    cudaGetSymbolAddress((void**)&res, g_res);
    cudaGetSymbolAddress((void**)&pooled, g_pooled);
    cudaGetSymbolAddress((void**)&e3, g_e3);
    cudaGetSymbolAddress((void**)&tt, g_t);
    cudaGetSymbolAddress((void**)&W21, g_W21);
    cudaGetSymbolAddress((void**)&RfH, g_RfH);
    cudaGetSymbolAddress((void**)&RfL, g_RfL);
    cudaGetSymbolAddress((void**)&AtH, g_AtH);
    cudaGetSymbolAddress((void**)&AtL, g_AtL);
    cudaGetSymbolAddress((void**)&Bh, g_Bh);
    cudaGetSymbolAddress((void**)&Bl, g_Bl);

    cudaFuncSetAttribute(mma_gemm, cudaFuncAttributeMaxDynamicSharedMemorySize, GEMM_SMEM);

    rownorm_kernel<<<NP, 256>>>(prior, Rf);
    conv_kernel<<<(NP * NP) / 1024, 256>>>(Rf, RfH, RfL);
    w21_kernel<<<32, 256>>>(W2, W1, W21);

    const float* Xf_cur = x;
    const float* Xa_cur = x;

    for (int step = 0; step < 2; step++) {
        pool_kernel<<<NP, 128>>>(Xa_cur, pooled);
        proj_kernel<<<NP / 16, 256>>>(pooled, W21, W3, tt, e3);
        sgemm_nt<<<dim3(NP / 128, NP / 128), 256>>>(tt, e3, attn, NP, NP, DD, 0);
        topp_kernel<<<NP, 512>>>(attn);
        conv_kernel<<<(NP * NP) / 1024, 256>>>(attn, AtH, AtL);

        // Xf = Rf @ Xf_cur
        conv_kernel<<<XTOT / 1024, 256>>>(Xf_cur, Bh, Bl);
        mma_gemm<<<dim3(NOUT / 128, NP / 128), 256, GEMM_SMEM>>>(RfH, RfL, Bh, Bl, xf);
        // Xa = attn @ Xa_cur  (step 0: Xa_cur == Xf_cur == x, conversion reusable)
        if (step > 0) conv_kernel<<<XTOT / 1024, 256>>>(Xa_cur, Bh, Bl);
        mma_gemm<<<dim3(NOUT / 128, NP / 128), 256, GEMM_SMEM>>>(AtH, AtL, Bh, Bl, xa);

        // residual += Xf@pfw^T + Xa@adw^T
        sgemm_nt<<<dim3(1, (NP * NC) / 128), 256>>>(xf, pfw + step * CC * CC, res,
                                                    NP * NC, CC, CC, step > 0 ? 1 : 0);
        sgemm_nt<<<dim3(1, (NP * NC) / 128), 256>>>(xa, adw + step * CC * CC, res,
                                                    NP * NC, CC, CC, 1);
        Xf_cur = xf;
        Xa_cur = xa;
    }

    ln_kernel<<<NP * NC, 128>>>(x, res, gamma, beta, alpha, out);
}

// round 8
// speedup vs baseline: 3.5354x; 1.2069x over previous
#include <cuda_runtime.h>
#include <cuda_bf16.h>
#include <math.h>
#include <stdint.h>

#define NP 2048
#define NC 64
#define CC 128
#define DD 64
#define NOUT (NC*CC)          // 8192
#define XTOT (NP*NOUT)

// ================= scratch (device globals; no allocation allowed) =========
__device__ __align__(16) float g_Rf[NP*NP];
__device__ __align__(16) float g_attn[NP*NP];          // logits buffer
__device__ __align__(16) float g_res[XTOT];
__device__ __align__(16) float g_pooled[NP*CC];
__device__ __align__(16) float g_e3[NP*DD];
__device__ __align__(16) float g_t[NP*DD];
__device__ __align__(16) float g_W21[DD*CC];
__device__ __align__(16) __nv_bfloat16 g_RfH[NP*NP];
__device__ __align__(16) __nv_bfloat16 g_RfL[NP*NP];
__device__ __align__(16) __nv_bfloat16 g_AtH[NP*NP];
__device__ __align__(16) __nv_bfloat16 g_AtL[NP*NP];
__device__ __align__(16) __nv_bfloat16 g_xH[XTOT];
__device__ __align__(16) __nv_bfloat16 g_xL[XTOT];
__device__ __align__(16) __nv_bfloat16 g_XfH[2][XTOT];
__device__ __align__(16) __nv_bfloat16 g_XfL[2][XTOT];
__device__ __align__(16) __nv_bfloat16 g_XaH[2][XTOT];
__device__ __align__(16) __nv_bfloat16 g_XaL[2][XTOT];
__device__ __align__(16) __nv_bfloat16 g_WTH[4*CC*CC]; // W^T hi: [c][d], mats: pfw0,adw0,pfw1,adw1
__device__ __align__(16) __nv_bfloat16 g_WTL[4*CC*CC];

// ================= PTX helpers (sm_80-era; valid on plain sm_103) ==========
__device__ __forceinline__ uint32_t smem_to_u32(const void* p) {
    uint32_t a;
    asm("{ .reg .u64 t; cvta.to.shared.u64 t, %1; cvt.u32.u64 %0, t; }" : "=r"(a) : "l"(p));
    return a;
}
__device__ __forceinline__ void cp16(uint32_t saddr, const void* g) {
    asm volatile("cp.async.cg.shared.global [%0], [%1], 16;" :: "r"(saddr), "l"(g) : "memory");
}
__device__ __forceinline__ void ldsm_x4(uint32_t* r, uint32_t addr) {
    asm volatile("ldmatrix.sync.aligned.m8n8.x4.shared.b16 {%0,%1,%2,%3}, [%4];"
        : "=r"(r[0]), "=r"(r[1]), "=r"(r[2]), "=r"(r[3]) : "r"(addr));
}
__device__ __forceinline__ void ldsm_x4_t(uint32_t* r, uint32_t addr) {
    asm volatile("ldmatrix.sync.aligned.m8n8.x4.trans.shared.b16 {%0,%1,%2,%3}, [%4];"
        : "=r"(r[0]), "=r"(r[1]), "=r"(r[2]), "=r"(r[3]) : "r"(addr));
}
__device__ __forceinline__ void mma_bf16(float* d, const uint32_t* a, uint32_t b0, uint32_t b1) {
    asm volatile(
        "mma.sync.aligned.m16n8k16.row.col.f32.bf16.bf16.f32 "
        "{%0,%1,%2,%3}, {%4,%5,%6,%7}, {%8,%9}, {%0,%1,%2,%3};"
        : "+f"(d[0]), "+f"(d[1]), "+f"(d[2]), "+f"(d[3])
        : "r"(a[0]), "r"(a[1]), "r"(a[2]), "r"(a[3]), "r"(b0), "r"(b1));
}

// ================= reductions ==============================================
__device__ __forceinline__ float blockReduceSum(float v, float* red) {
    int lane = threadIdx.x & 31, wid = threadIdx.x >> 5;
    #pragma unroll
    for (int o = 16; o; o >>= 1) v += __shfl_xor_sync(0xffffffffu, v, o);
    if (lane == 0) red[wid] = v;
    __syncthreads();
    int nw = (blockDim.x + 31) >> 5;
    float r = (wid == 0 && lane < nw) ? red[lane] : 0.f;
    if (wid == 0) {
        #pragma unroll
        for (int o = 16; o; o >>= 1) r += __shfl_xor_sync(0xffffffffu, r, o);
        if (lane == 0) red[0] = r;
    }
    __syncthreads();
    r = red[0];
    __syncthreads();
    return r;
}
__device__ __forceinline__ float blockReduceMax(float v, float* red) {
    int lane = threadIdx.x & 31, wid = threadIdx.x >> 5;
    #pragma unroll
    for (int o = 16; o; o >>= 1) v = fmaxf(v, __shfl_xor_sync(0xffffffffu, v, o));
    if (lane == 0) red[wid] = v;
    __syncthreads();
    int nw = (blockDim.x + 31) >> 5;
    float r = (wid == 0 && lane < nw) ? red[lane] : -INFINITY;
    if (wid == 0) {
        #pragma unroll
        for (int o = 16; o; o >>= 1) r = fmaxf(r, __shfl_xor_sync(0xffffffffu, r, o));
        if (lane == 0) red[0] = r;
    }
    __syncthreads();
    r = red[0];
    __syncthreads();
    return r;
}

// ================= small kernels ===========================================
__global__ void rownorm_kernel(const float* __restrict__ prior, float* __restrict__ Rf) {
    __shared__ float red[32];
    int i = blockIdx.x, t = threadIdx.x;
    const float* row = prior + (size_t)i * NP;
    float s = 0.f;
    for (int j = t; j < NP; j += 256) s += row[j];
    s = blockReduceSum(s, red);
    float inv = 1.f / fmaxf(s, 1e-12f);
    float* orow = Rf + (size_t)i * NP;
    for (int j = t; j < NP; j += 256) orow[j] = row[j] * inv;
}

__global__ void pool_kernel(const float* __restrict__ Xa, float* __restrict__ pooled) {
    int i = blockIdx.x, c = threadIdx.x;  // 128 threads
    const float* base = Xa + (size_t)i * (NC * CC) + c;
    float s = 0.f;
    #pragma unroll
    for (int k = 0; k < NC; k++) s += base[k * CC];
    pooled[i * CC + c] = s * (1.f / NC);
}

__global__ void pool_bf16_kernel(const __nv_bfloat16* __restrict__ H,
                                 const __nv_bfloat16* __restrict__ L,
                                 float* __restrict__ pooled) {
    int i = blockIdx.x, c = threadIdx.x;  // 128 threads
    size_t base = (size_t)i * (NC * CC) + c;
    float s = 0.f;
    #pragma unroll
    for (int k = 0; k < NC; k++)
        s += __bfloat162float(H[base + k * CC]) + __bfloat162float(L[base + k * CC]);
    pooled[i * CC + c] = s * (1.f / NC);
}

// W21 = W2 @ W1  : (64 x 128), K=64
__global__ void w21_kernel(const float* __restrict__ W2, const float* __restrict__ W1,
                           float* __restrict__ W21) {
    int idx = blockIdx.x * 256 + threadIdx.x;
    int d = idx >> 7, c = idx & 127;
    float s = 0.f;
    for (int e = 0; e < DD; e++) s += W2[d * DD + e] * W1[e * CC + c];
    W21[idx] = s;
}

// transpose + hi/lo split of delta weights: WT[m][c][d] from W[m][d][c]
__global__ void wt_kernel(const float* __restrict__ pfw, const float* __restrict__ adw,
                          __nv_bfloat16* __restrict__ WTH, __nv_bfloat16* __restrict__ WTL) {
    int c = blockIdx.x, m = blockIdx.y, d = threadIdx.x;
    const float* W = (m & 1) ? adw : pfw;
    W += (m >> 1) * CC * CC;
    float v = W[d * CC + c];
    __nv_bfloat16 h = __float2bfloat16_rn(v);
    WTH[(size_t)m * CC * CC + c * CC + d] = h;
    WTL[(size_t)m * CC * CC + c * CC + d] = __float2bfloat16_rn(v - __bfloat162float(h));
}

// t = pooled @ W21^T ; e3 = pooled @ W3^T   (2048 x 64, K=128)
__global__ void __launch_bounds__(256) proj_kernel(const float* __restrict__ pooled,
                                                   const float* __restrict__ W21,
                                                   const float* __restrict__ W3,
                                                   float* __restrict__ t_out,
                                                   float* __restrict__ e3_out) {
    __shared__ float sp[16][CC];
    int row0 = blockIdx.x * 16;
    int tid = threadIdx.x;
    for (int i = tid; i < 16 * CC; i += 256)
        sp[i >> 7][i & 127] = pooled[(size_t)(row0 + (i >> 7)) * CC + (i & 127)];
    __syncthreads();
    int n = tid & 63, rq = tid >> 6;
    float at[4] = {0, 0, 0, 0}, ae[4] = {0, 0, 0, 0};
    for (int c = 0; c < CC; c++) {
        float w21 = __ldg(&W21[n * CC + c]);
        float w3  = __ldg(&W3[n * CC + c]);
        #pragma unroll
        for (int j = 0; j < 4; j++) {
            float p = sp[rq + 4 * j][c];
            at[j] = fmaf(p, w21, at[j]);
            ae[j] = fmaf(p, w3, ae[j]);
        }
    }
    #pragma unroll
    for (int j = 0; j < 4; j++) {
        int r = row0 + rq + 4 * j;
        t_out[r * DD + n] = at[j];
        e3_out[r * DD + n] = ae[j];
    }
}

// fp32 -> (hi, lo) bf16, same layout
__global__ void conv_kernel(const float* __restrict__ A,
                            __nv_bfloat16* __restrict__ H, __nv_bfloat16* __restrict__ L) {
    size_t i = (size_t)(blockIdx.x * 256 + threadIdx.x) * 4;
    float4 v = *(const float4*)(A + i);
    __nv_bfloat16 h0 = __float2bfloat16_rn(v.x), h1 = __float2bfloat16_rn(v.y);
    __nv_bfloat16 h2 = __float2bfloat16_rn(v.z), h3 = __float2bfloat16_rn(v.w);
    __nv_bfloat162 hh0; hh0.x = h0; hh0.y = h1;
    __nv_bfloat162 hh1; hh1.x = h2; hh1.y = h3;
    __nv_bfloat162 ll0, ll1;
    ll0.x = __float2bfloat16_rn(v.x - __bfloat162float(h0));
    ll0.y = __float2bfloat16_rn(v.y - __bfloat162float(h1));
    ll1.x = __float2bfloat16_rn(v.z - __bfloat162float(h2));
    ll1.y = __float2bfloat16_rn(v.w - __bfloat162float(h3));
    *(__nv_bfloat162*)(H + i) = hh0; *(__nv_bfloat162*)(H + i + 2) = hh1;
    *(__nv_bfloat162*)(L + i) = ll0; *(__nv_bfloat162*)(L + i + 2) = ll1;
}

// ================= split-bf16 HMMA GEMM (big) ==============================
// C[2048 x 8192] = A[2048 x 2048] @ B[2048 x 8192]; A,B hi/lo bf16 row-major.
// Output written as hi/lo bf16 pair (exact to ~2^-16 rel of the fp32 acc).
#define GEMM_SMEM (2 * 65536)

__global__ void __launch_bounds__(256, 1) mma_gemm(
    const __nv_bfloat16* __restrict__ Ah, const __nv_bfloat16* __restrict__ Al,
    const __nv_bfloat16* __restrict__ Bh, const __nv_bfloat16* __restrict__ Bl,
    __nv_bfloat16* __restrict__ CH, __nv_bfloat16* __restrict__ CL) {
    extern __shared__ char smem[];
    uint32_t sbase = smem_to_u32(smem);
    int tid = threadIdx.x, wid = tid >> 5, lane = tid & 31;
    int bm = blockIdx.y * 128, bn = blockIdx.x * 128;
    int wm = (wid >> 1) * 32;
    int wn = (wid & 1) * 64;

    float acc[2][8][4];
    #pragma unroll
    for (int i = 0; i < 2; i++)
        #pragma unroll
        for (int j = 0; j < 8; j++)
            #pragma unroll
            for (int q = 0; q < 4; q++) acc[i][j][q] = 0.f;

    const int NCHUNK = NP / 64;

    auto load_chunk = [&](int ch, int buf) {
        int k0 = ch * 64;
        uint32_t s = sbase + buf * 65536;
        #pragma unroll
        for (int t = 0; t < 4; t++) {
            int i = tid + t * 256;
            int r = i >> 3, c = i & 7;
            uint32_t off = r * 128 + c * 16;
            uint32_t sw = off ^ (((off >> 7) & 7) << 4);
            const char* gh = (const char*)(Ah + (size_t)(bm + r) * NP + k0) + c * 16;
            const char* gl = (const char*)(Al + (size_t)(bm + r) * NP + k0) + c * 16;
            cp16(s + sw, gh);
            cp16(s + 16384 + sw, gl);
        }
        #pragma unroll
        for (int t = 0; t < 4; t++) {
            int i = tid + t * 256;
            int k = i >> 4, n = i & 15;
            uint32_t off = k * 256 + n * 16;
            uint32_t sw = off ^ (((off >> 8) & 7) << 4);
            const char* gh = (const char*)(Bh + (size_t)(k0 + k) * NOUT + bn) + n * 16;
            const char* gl = (const char*)(Bl + (size_t)(k0 + k) * NOUT + bn) + n * 16;
            cp16(s + 32768 + sw, gh);
            cp16(s + 49152 + sw, gl);
        }
        asm volatile("cp.async.commit_group;" ::: "memory");
    };

    load_chunk(0, 0);

    for (int ch = 0; ch < NCHUNK; ch++) {
        if (ch + 1 < NCHUNK) load_chunk(ch + 1, (ch + 1) & 1);
        if (ch + 1 < NCHUNK) asm volatile("cp.async.wait_group 1;" ::: "memory");
        else                 asm volatile("cp.async.wait_group 0;" ::: "memory");
        __syncthreads();

        uint32_t s = sbase + (ch & 1) * 65536;
        uint32_t sAh = s, sAl = s + 16384, sBh = s + 32768, sBl = s + 49152;

        #pragma unroll
        for (int kk = 0; kk < 64; kk += 16) {
            uint32_t ah[2][4], al[2][4], bh[4][4], bl[4][4];
            #pragma unroll
            for (int p = 0; p < 2; p++) {
                uint32_t off = (uint32_t)(wm + 16 * p + (lane & 15)) * 128
                             + kk * 2 + (lane >> 4) * 16;
                uint32_t sw = off ^ (((off >> 7) & 7) << 4);
                ldsm_x4(ah[p], sAh + sw);
                ldsm_x4(al[p], sAl + sw);
            }
            #pragma unroll
            for (int p = 0; p < 4; p++) {
                uint32_t off = (uint32_t)(kk + (lane & 15)) * 256
                             + (wn + p * 16) * 2 + (lane >> 4) * 16;
                uint32_t sw = off ^ (((off >> 8) & 7) << 4);
                ldsm_x4_t(bh[p], sBh + sw);
                ldsm_x4_t(bl[p], sBl + sw);
            }
            #pragma unroll
            for (int i = 0; i < 2; i++)
                #pragma unroll
                for (int j = 0; j < 8; j++)
                    mma_bf16(acc[i][j], ah[i], bh[j >> 1][(j & 1) * 2], bh[j >> 1][(j & 1) * 2 + 1]);
            #pragma unroll
            for (int i = 0; i < 2; i++)
                #pragma unroll
                for (int j = 0; j < 8; j++)
                    mma_bf16(acc[i][j], al[i], bh[j >> 1][(j & 1) * 2], bh[j >> 1][(j & 1) * 2 + 1]);
            #pragma unroll
            for (int i = 0; i < 2; i++)
                #pragma unroll
                for (int j = 0; j < 8; j++)
                    mma_bf16(acc[i][j], ah[i], bl[j >> 1][(j & 1) * 2], bl[j >> 1][(j & 1) * 2 + 1]);
        }
        __syncthreads();
    }

    // epilogue: split fp32 acc into hi/lo bf16
    int grp = lane >> 2, tig = lane & 3;
    #pragma unroll
    for (int i = 0; i < 2; i++)
        #pragma unroll
        for (int j = 0; j < 8; j++) {
            int row = bm + wm + 16 * i + grp;
            int col = bn + wn + 8 * j + 2 * tig;
            #pragma unroll
            for (int half = 0; half < 2; half++) {
                float a0 = acc[i][j][half * 2], a1 = acc[i][j][half * 2 + 1];
                __nv_bfloat16 h0 = __float2bfloat16_rn(a0);
                __nv_bfloat16 h1 = __float2bfloat16_rn(a1);
                __nv_bfloat162 hh; hh.x = h0; hh.y = h1;
                __nv_bfloat162 ll;
                ll.x = __float2bfloat16_rn(a0 - __bfloat162float(h0));
                ll.y = __float2bfloat16_rn(a1 - __bfloat162float(h1));
                size_t o = (size_t)(row + half * 8) * NOUT + col;
                *(__nv_bfloat162*)(CH + o) = hh;
                *(__nv_bfloat162*)(CL + o) = ll;
            }
        }
}

// ================= fused delta HMMA: res (+)= Xf@pfw^T + Xa@adw^T ==========
// X arrays [131072 x 128] bf16 hi/lo; WT [128 c][128 d] bf16 hi/lo (row-major).
// CTA: 128 rows x 128 d, K=128 in 2 chunks of 64, single smem buffer (128KB).
#define DELTA_SMEM (8 * 16384)

__global__ void __launch_bounds__(256, 1) delta_gemm(
    const __nv_bfloat16* __restrict__ XfH, const __nv_bfloat16* __restrict__ XfL,
    const __nv_bfloat16* __restrict__ XaH, const __nv_bfloat16* __restrict__ XaL,
    const __nv_bfloat16* __restrict__ WpH, const __nv_bfloat16* __restrict__ WpL,
    const __nv_bfloat16* __restrict__ WaH, const __nv_bfloat16* __restrict__ WaL,
    float* __restrict__ res, int accumulate) {
    extern __shared__ char smem[];
    uint32_t sbase = smem_to_u32(smem);
    int tid = threadIdx.x, wid = tid >> 5, lane = tid & 31;
    int bm = blockIdx.x * 128;
    int wm = (wid >> 1) * 32;
    int wn = (wid & 1) * 64;

    // smem: XfH@0 XfL@16K XaH@32K XaL@48K (128 rows x 128B each)
    //       WpH@64K WpL@80K WaH@96K WaL@112K (64 c-rows x 256B each)
    float acc[2][8][4];
    #pragma unroll
    for (int i = 0; i < 2; i++)
        #pragma unroll
        for (int j = 0; j < 8; j++)
            #pragma unroll
            for (int q = 0; q < 4; q++) acc[i][j][q] = 0.f;

    for (int cb = 0; cb < 2; cb++) {
        int c0 = cb * 64;
        // X tiles (A-style)
        #pragma unroll
        for (int t = 0; t < 4; t++) {
            int i = tid + t * 256;
            int r = i >> 3, c = i & 7;
            uint32_t off = r * 128 + c * 16;
            uint32_t sw = off ^ (((off >> 7) & 7) << 4);
            const char* p0 = (const char*)(XfH + (size_t)(bm + r) * CC + c0) + c * 16;
            const char* p1 = (const char*)(XfL + (size_t)(bm + r) * CC + c0) + c * 16;
            const char* p2 = (const char*)(XaH + (size_t)(bm + r) * CC + c0) + c * 16;
            const char* p3 = (const char*)(XaL + (size_t)(bm + r) * CC + c0) + c * 16;
            cp16(sbase + sw, p0);
            cp16(sbase + 16384 + sw, p1);
            cp16(sbase + 32768 + sw, p2);
            cp16(sbase + 49152 + sw, p3);
        }
        // W tiles (B-style)
        #pragma unroll
        for (int t = 0; t < 4; t++) {
            int i = tid + t * 256;
            int k = i >> 4, n = i & 15;
            uint32_t off = k * 256 + n * 16;
            uint32_t sw = off ^ (((off >> 8) & 7) << 4);
            const char* p0 = (const char*)(WpH + (size_t)(c0 + k) * CC) + n * 16;
            const char* p1 = (const char*)(WpL + (size_t)(c0 + k) * CC) + n * 16;
            const char* p2 = (const char*)(WaH + (size_t)(c0 + k) * CC) + n * 16;
            const char* p3 = (const char*)(WaL + (size_t)(c0 + k) * CC) + n * 16;
            cp16(sbase + 65536 + sw, p0);
            cp16(sbase + 81920 + sw, p1);
            cp16(sbase + 98304 + sw, p2);
            cp16(sbase + 114688 + sw, p3);
        }
        asm volatile("cp.async.commit_group;" ::: "memory");
        asm volatile("cp.async.wait_group 0;" ::: "memory");
        __syncthreads();

        #pragma unroll
        for (int kk = 0; kk < 64; kk += 16) {
            // ---- Xf path ----
            {
                uint32_t ah[2][4], al[2][4], bh[4][4], bl[4][4];
                #pragma unroll
                for (int p = 0; p < 2; p++) {
                    uint32_t off = (uint32_t)(wm + 16 * p + (lane & 15)) * 128
                                 + kk * 2 + (lane >> 4) * 16;
                    uint32_t sw = off ^ (((off >> 7) & 7) << 4);
                    ldsm_x4(ah[p], sbase + sw);
                    ldsm_x4(al[p], sbase + 16384 + sw);
                }
                #pragma unroll
                for (int p = 0; p < 4; p++) {
                    uint32_t off = (uint32_t)(kk + (lane & 15)) * 256
                                 + (wn + p * 16) * 2 + (lane >> 4) * 16;
                    uint32_t sw = off ^ (((off >> 8) & 7) << 4);
                    ldsm_x4_t(bh[p], sbase + 65536 + sw);
                    ldsm_x4_t(bl[p], sbase + 81920 + sw);
                }
                #pragma unroll
                for (int i = 0; i < 2; i++)
                    #pragma unroll
                    for (int j = 0; j < 8; j++)
                        mma_bf16(acc[i][j], ah[i], bh[j >> 1][(j & 1) * 2], bh[j >> 1][(j & 1) * 2 + 1]);
                #pragma unroll
                for (int i = 0; i < 2; i++)
                    #pragma unroll
                    for (int j = 0; j < 8; j++)
                        mma_bf16(acc[i][j], al[i], bh[j >> 1][(j & 1) * 2], bh[j >> 1][(j & 1) * 2 + 1]);
                #pragma unroll
                for (int i = 0; i < 2; i++)
                    #pragma unroll
                    for (int j = 0; j < 8; j++)
                        mma_bf16(acc[i][j], ah[i], bl[j >> 1][(j & 1) * 2], bl[j >> 1][(j & 1) * 2 + 1]);
            }
            // ---- Xa path ----
            {
                uint32_t ah[2][4], al[2][4], bh[4][4], bl[4][4];
                #pragma unroll
                for (int p = 0; p < 2; p++) {
                    uint32_t off = (uint32_t)(wm + 16 * p + (lane & 15)) * 128
                                 + kk * 2 + (lane >> 4) * 16;
                    uint32_t sw = off ^ (((off >> 7) & 7) << 4);
                    ldsm_x4(ah[p], sbase + 32768 + sw);
                    ldsm_x4(al[p], sbase + 49152 + sw);
                }
                #pragma unroll
                for (int p = 0; p < 4; p++) {
                    uint32_t off = (uint32_t)(kk + (lane & 15)) * 256
                                 + (wn + p * 16) * 2 + (lane >> 4) * 16;
                    uint32_t sw = off ^ (((off >> 8) & 7) << 4);
                    ldsm_x4_t(bh[p], sbase + 98304 + sw);
                    ldsm_x4_t(bl[p], sbase + 114688 + sw);
                }
                #pragma unroll
                for (int i = 0; i < 2; i++)
                    #pragma unroll
                    for (int j = 0; j < 8; j++)
                        mma_bf16(acc[i][j], ah[i], bh[j >> 1][(j & 1) * 2], bh[j >> 1][(j & 1) * 2 + 1]);
                #pragma unroll
                for (int i = 0; i < 2; i++)
                    #pragma unroll
                    for (int j = 0; j < 8; j++)
                        mma_bf16(acc[i][j], al[i], bh[j >> 1][(j & 1) * 2], bh[j >> 1][(j & 1) * 2 + 1]);
                #pragma unroll
                for (int i = 0; i < 2; i++)
                    #pragma unroll
                    for (int j = 0; j < 8; j++)
                        mma_bf16(acc[i][j], ah[i], bl[j >> 1][(j & 1) * 2], bl[j >> 1][(j & 1) * 2 + 1]);
            }
        }
        __syncthreads();
    }

    int grp = lane >> 2, tig = lane & 3;
    #pragma unroll
    for (int i = 0; i < 2; i++)
        #pragma unroll
        for (int j = 0; j < 8; j++) {
            int row = bm + wm + 16 * i + grp;
            int col = wn + 8 * j + 2 * tig;
            float* d0 = res + (size_t)row * CC + col;
            float* d1 = res + (size_t)(row + 8) * CC + col;
            if (accumulate) {
                float2 c0 = *(float2*)d0, c1 = *(float2*)d1;
                *(float2*)d0 = make_float2(c0.x + acc[i][j][0], c0.y + acc[i][j][1]);
                *(float2*)d1 = make_float2(c1.x + acc[i][j][2], c1.y + acc[i][j][3]);
            } else {
                *(float2*)d0 = make_float2(acc[i][j][0], acc[i][j][1]);
                *(float2*)d1 = make_float2(acc[i][j][2], acc[i][j][3]);
            }
        }
}

// ================= fp32 tiled NT (logits only) =============================
__global__ void __launch_bounds__(256) sgemm_nt(const float* __restrict__ A,
                                                const float* __restrict__ B,
                                                float* __restrict__ C,
                                                int M, int N, int K) {
    __shared__ __align__(16) float As[8][128];
    __shared__ __align__(16) float Bs[8][128];
    int tid = threadIdx.x;
    int bm = blockIdx.y * 128, bn = blockIdx.x * 128;
    int tr = (tid >> 4) << 3;
    int tc = (tid & 15) << 3;
    int aRow = tid >> 1, aCol = (tid & 1) << 2;
    int bN = tid >> 1, bK = (tid & 1) << 2;
    const float* Ap = A + (size_t)(bm + aRow) * K + aCol;
    const float* Bp = B + (size_t)(bn + bN) * K + bK;
    float acc[8][8];
    #pragma unroll
    for (int i = 0; i < 8; i++)
        #pragma unroll
        for (int j = 0; j < 8; j++) acc[i][j] = 0.f;
    for (int k0 = 0; k0 < K; k0 += 8) {
        float4 av = *(const float4*)(Ap + k0);
        As[aCol + 0][aRow] = av.x; As[aCol + 1][aRow] = av.y;
        As[aCol + 2][aRow] = av.z; As[aCol + 3][aRow] = av.w;
        float4 bv = *(const float4*)(Bp + k0);
        Bs[bK + 0][bN] = bv.x; Bs[bK + 1][bN] = bv.y;
        Bs[bK + 2][bN] = bv.z; Bs[bK + 3][bN] = bv.w;
        __syncthreads();
        #pragma unroll
        for (int kk = 0; kk < 8; kk++) {
            float4 a0 = *(const float4*)&As[kk][tr];
            float4 a1 = *(const float4*)&As[kk][tr + 4];
            float4 b0 = *(const float4*)&Bs[kk][tc];
            float4 b1 = *(const float4*)&Bs[kk][tc + 4];
            float ar[8] = {a0.x, a0.y, a0.z, a0.w, a1.x, a1.y, a1.z, a1.w};
            float br[8] = {b0.x, b0.y, b0.z, b0.w, b1.x, b1.y, b1.z, b1.w};
            #pragma unroll
            for (int i = 0; i < 8; i++)
                #pragma unroll
                for (int j = 0; j < 8; j++) acc[i][j] = fmaf(ar[i], br[j], acc[i][j]);
        }
        __syncthreads();
    }
    #pragma unroll
    for (int i = 0; i < 8; i++) {
        float* crow = C + (size_t)(bm + tr + i) * N + bn + tc;
        *(float4*)(crow)     = make_float4(acc[i][0], acc[i][1], acc[i][2], acc[i][3]);
        *(float4*)(crow + 4) = make_float4(acc[i][4], acc[i][5], acc[i][6], acc[i][7]);
    }
}

// ================= softmax + top-p via threshold bisection =================
// thr = s[m] is the unique largest value v with F(v) = sum_{a_j >= v} a_j >= p.
// 54 bisection steps shrink [lo,hi) around thr to sub-ulp width; then
// thr = max{a_j : a_j < hi} exactly. Writes masked/renormed attn as bf16 hi/lo.
__global__ void __launch_bounds__(512) topp_kernel(const float* __restrict__ logits,
                                                   __nv_bfloat16* __restrict__ H,
                                                   __nv_bfloat16* __restrict__ L) {
    const float P = 0.9f;
    __shared__ float red[32];
    int t = threadIdx.x;
    const float* row = logits + (size_t)blockIdx.x * NP;

    float v[4], mx = -INFINITY;
    #pragma unroll
    for (int e = 0; e < 4; e++) { v[e] = row[t + e * 512]; mx = fmaxf(mx, v[e]); }
    mx = blockReduceMax(mx, red);
    float z = 0.f;
    #pragma unroll
    for (int e = 0; e < 4; e++) { v[e] = expf(v[e] - mx); z += v[e]; }
    z = blockReduceSum(z, red);
    float invZ = 1.f / z;
    #pragma unroll
    for (int e = 0; e < 4; e++) v[e] *= invZ;

    // max prob == invZ (the max-logit element maps to exp(0)*invZ)
    float lo = 0.f, hi = invZ * 1.000001f + 1e-37f;
    for (int it = 0; it < 54; it++) {
        float mid = 0.5f * (lo + hi);
        float p = 0.f;
        #pragma unroll
        for (int e = 0; e < 4; e++) if (v[e] >= mid) p += v[e];
        p = blockReduceSum(p, red);
        if (p >= P) lo = mid; else hi = mid;
    }
    float cand = -INFINITY;
    #pragma unroll
    for (int e = 0; e < 4; e++) if (v[e] < hi) cand = fmaxf(cand, v[e]);
    float thr = blockReduceMax(cand, red);

    float msum = 0.f, mv[4];
    #pragma unroll
    for (int e = 0; e < 4; e++) {
        mv[e] = (v[e] >= thr) ? v[e] : 0.f;
        msum += mv[e];
    }
    msum = blockReduceSum(msum, red);
    float inv = 1.f / fmaxf(msum, 1e-12f);
    size_t base = (size_t)blockIdx.x * NP;
    #pragma unroll
    for (int e = 0; e < 4; e++) {
        float o = mv[e] * inv;
        __nv_bfloat16 h = __float2bfloat16_rn(o);
        H[base + t + e * 512] = h;
        L[base + t + e * 512] = __float2bfloat16_rn(o - __bfloat162float(h));
    }
}

// ================= gate + residual + layernorm =============================
__global__ void __launch_bounds__(128) ln_kernel(const float* __restrict__ x,
                                                 const float* __restrict__ res,
                                                 const float* __restrict__ gamma,
                                                 const float* __restrict__ beta,
                                                 const float* __restrict__ alpha,
                                                 float* __restrict__ out) {
    __shared__ float red[32];
    int row = blockIdx.x, c = threadIdx.x;
    float gate = 1.f / (1.f + expf(-alpha[0]));
    size_t idx = (size_t)row * CC + c;
    float h = x[idx] + gate * res[idx];
    float mu = blockReduceSum(h, red) * (1.f / CC);
    float d = h - mu;
    float var = blockReduceSum(d * d, red) * (1.f / CC);
    out[idx] = d * rsqrtf(var + 1e-5f) * gamma[c] + beta[c];
}

// ================= launch ==================================================
extern "C" void kernel_launch(void* const* d_in, const int* in_sizes, int n_in,
                              void* d_out, int out_size) {
    const float* x     = (const float*)d_in[0];
    const float* prior = (const float*)d_in[1];
    const float* W1    = (const float*)d_in[2];
    const float* W2    = (const float*)d_in[3];
    const float* W3    = (const float*)d_in[4];
    const float* pfw   = (const float*)d_in[5];
    const float* adw   = (const float*)d_in[6];
    const float* gamma = (const float*)d_in[7];
    const float* beta  = (const float*)d_in[8];
    const float* alpha = (const float*)d_in[9];
    float* out = (float*)d_out;

    float *Rf, *attn, *res, *pooled, *e3, *tt, *W21;
    __nv_bfloat16 *RfH, *RfL, *AtH, *AtL, *xH, *xL, *XfH, *XfL, *XaH, *XaL, *WTH, *WTL;
    cudaGetSymbolAddress((void**)&Rf, g_Rf);
    cudaGetSymbolAddress((void**)&attn, g_attn);
    cudaGetSymbolAddress((void**)&res, g_res);
    cudaGetSymbolAddress((void**)&pooled, g_pooled);
    cudaGetSymbolAddress((void**)&e3, g_e3);
    cudaGetSymbolAddress((void**)&tt, g_t);
    cudaGetSymbolAddress((void**)&W21, g_W21);
    cudaGetSymbolAddress((void**)&RfH, g_RfH);
    cudaGetSymbolAddress((void**)&RfL, g_RfL);
    cudaGetSymbolAddress((void**)&AtH, g_AtH);
    cudaGetSymbolAddress((void**)&AtL, g_AtL);
    cudaGetSymbolAddress((void**)&xH, g_xH);
    cudaGetSymbolAddress((void**)&xL, g_xL);
    cudaGetSymbolAddress((void**)&XfH, g_XfH);
    cudaGetSymbolAddress((void**)&XfL, g_XfL);
    cudaGetSymbolAddress((void**)&XaH, g_XaH);
    cudaGetSymbolAddress((void**)&XaL, g_XaL);
    cudaGetSymbolAddress((void**)&WTH, g_WTH);
    cudaGetSymbolAddress((void**)&WTL, g_WTL);

    cudaFuncSetAttribute(mma_gemm, cudaFuncAttributeMaxDynamicSharedMemorySize, GEMM_SMEM);
    cudaFuncSetAttribute(delta_gemm, cudaFuncAttributeMaxDynamicSharedMemorySize, DELTA_SMEM);

    rownorm_kernel<<<NP, 256>>>(prior, Rf);
    conv_kernel<<<(NP * NP) / 1024, 256>>>(Rf, RfH, RfL);
    conv_kernel<<<XTOT / 1024, 256>>>(x, xH, xL);
    w21_kernel<<<32, 256>>>(W2, W1, W21);
    wt_kernel<<<dim3(CC, 4), CC>>>(pfw, adw, WTH, WTL);

    for (int step = 0; step < 2; step++) {
        // pooled from previous Xa
        if (step == 0)
            pool_kernel<<<NP, 128>>>(x, pooled);
        else
            pool_bf16_kernel<<<NP, 128>>>(XaH, XaL, pooled);   // set 0 from step 0

        proj_kernel<<<NP / 16, 256>>>(pooled, W21, W3, tt, e3);
        sgemm_nt<<<dim3(NP / 128, NP / 128), 256>>>(tt, e3, attn, NP, NP, DD);
        topp_kernel<<<NP, 512>>>(attn, AtH, AtL);

        const __nv_bfloat16* BfH = (step == 0) ? xH : XfH;        // Xf input
        const __nv_bfloat16* BfL = (step == 0) ? xL : XfL;
        const __nv_bfloat16* BaH = (step == 0) ? xH : XaH;        // Xa input
        const __nv_bfloat16* BaL = (step == 0) ? xL : XaL;
        __nv_bfloat16* OfH = XfH + (size_t)step * XTOT;
        __nv_bfloat16* OfL = XfL + (size_t)step * XTOT;
        __nv_bfloat16* OaH = XaH + (size_t)step * XTOT;
        __nv_bfloat16* OaL = XaL + (size_t)step * XTOT;

        mma_gemm<<<dim3(NOUT / 128, NP / 128), 256, GEMM_SMEM>>>(RfH, RfL, BfH, BfL, OfH, OfL);
        mma_gemm<<<dim3(NOUT / 128, NP / 128), 256, GEMM_SMEM>>>(AtH, AtL, BaH, BaL, OaH, OaL);

        const __nv_bfloat16* wp_h = WTH + (size_t)(2 * step + 0) * CC * CC;
        const __nv_bfloat16* wp_l = WTL + (size_t)(2 * step + 0) * CC * CC;
        const __nv_bfloat16* wa_h = WTH + (size_t)(2 * step + 1) * CC * CC;
        const __nv_bfloat16* wa_l = WTL + (size_t)(2 * step + 1) * CC * CC;
        delta_gemm<<<(NP * NC) / 128, 256, DELTA_SMEM>>>(
            OfH, OfL, OaH, OaL, wp_h, wp_l, wa_h, wa_l, res, step);
    }

    ln_kernel<<<NP * NC, 128>>>(x, res, gamma, beta, alpha, out);
}

// round 13
// speedup vs baseline: 3.7005x; 1.0467x over previous
#include <cuda_runtime.h>
#include <cuda_bf16.h>
#include <math.h>
#include <stdint.h>

#define NP 2048
#define NC 64
#define CC 128
#define DD 64
#define NOUT (NC*CC)          // 8192
#define XTOT (NP*NOUT)

// ================= scratch (device globals; no allocation allowed) =========
__device__ __align__(16) float g_Rf[NP*NP];
__device__ __align__(16) float g_attn[NP*NP];          // logits buffer
__device__ __align__(16) float g_res[XTOT];
__device__ __align__(16) float g_pooled[NP*CC];
__device__ __align__(16) float g_e3[NP*DD];
__device__ __align__(16) float g_t[NP*DD];
__device__ __align__(16) float g_W21[DD*CC];
__device__ __align__(16) __nv_bfloat16 g_RfH[NP*NP];
__device__ __align__(16) __nv_bfloat16 g_RfL[NP*NP];
__device__ __align__(16) __nv_bfloat16 g_AtH[NP*NP];
__device__ __align__(16) __nv_bfloat16 g_AtL[NP*NP];
__device__ __align__(16) __nv_bfloat16 g_xH[XTOT];
__device__ __align__(16) __nv_bfloat16 g_xL[XTOT];
__device__ __align__(16) __nv_bfloat16 g_XfH[2][XTOT];
__device__ __align__(16) __nv_bfloat16 g_XfL[2][XTOT];
__device__ __align__(16) __nv_bfloat16 g_XaH[2][XTOT];
__device__ __align__(16) __nv_bfloat16 g_XaL[2][XTOT];
__device__ __align__(16) __nv_bfloat16 g_WTH[4*CC*CC]; // W^T hi: [c][d]
__device__ __align__(16) __nv_bfloat16 g_WTL[4*CC*CC];

// ================= PTX helpers (sm_80-era; valid on plain sm_103) ==========
__device__ __forceinline__ uint32_t smem_to_u32(const void* p) {
    uint32_t a;
    asm("{ .reg .u64 t; cvta.to.shared.u64 t, %1; cvt.u32.u64 %0, t; }" : "=r"(a) : "l"(p));
    return a;
}
__device__ __forceinline__ void cp16(uint32_t saddr, const void* g) {
    asm volatile("cp.async.cg.shared.global [%0], [%1], 16;" :: "r"(saddr), "l"(g) : "memory");
}
__device__ __forceinline__ void ldsm_x4(uint32_t* r, uint32_t addr) {
    asm volatile("ldmatrix.sync.aligned.m8n8.x4.shared.b16 {%0,%1,%2,%3}, [%4];"
        : "=r"(r[0]), "=r"(r[1]), "=r"(r[2]), "=r"(r[3]) : "r"(addr));
}
__device__ __forceinline__ void ldsm_x4_t(uint32_t* r, uint32_t addr) {
    asm volatile("ldmatrix.sync.aligned.m8n8.x4.trans.shared.b16 {%0,%1,%2,%3}, [%4];"
        : "=r"(r[0]), "=r"(r[1]), "=r"(r[2]), "=r"(r[3]) : "r"(addr));
}
__device__ __forceinline__ void mma_bf16(float* d, const uint32_t* a, uint32_t b0, uint32_t b1) {
    asm volatile(
        "mma.sync.aligned.m16n8k16.row.col.f32.bf16.bf16.f32 "
        "{%0,%1,%2,%3}, {%4,%5,%6,%7}, {%8,%9}, {%0,%1,%2,%3};"
        : "+f"(d[0]), "+f"(d[1]), "+f"(d[2]), "+f"(d[3])
        : "r"(a[0]), "r"(a[1]), "r"(a[2]), "r"(a[3]), "r"(b0), "r"(b1));
}

// ================= reductions ==============================================
__device__ __forceinline__ float blockReduceSum(float v, float* red) {
    int lane = threadIdx.x & 31, wid = threadIdx.x >> 5;
    #pragma unroll
    for (int o = 16; o; o >>= 1) v += __shfl_xor_sync(0xffffffffu, v, o);
    if (lane == 0) red[wid] = v;
    __syncthreads();
    int nw = (blockDim.x + 31) >> 5;
    float r = (wid == 0 && lane < nw) ? red[lane] : 0.f;
    if (wid == 0) {
        #pragma unroll
        for (int o = 16; o; o >>= 1) r += __shfl_xor_sync(0xffffffffu, r, o);
        if (lane == 0) red[0] = r;
    }
    __syncthreads();
    r = red[0];
    __syncthreads();
    return r;
}
__device__ __forceinline__ float blockReduceMax(float v, float* red) {
    int lane = threadIdx.x & 31, wid = threadIdx.x >> 5;
    #pragma unroll
    for (int o = 16; o; o >>= 1) v = fmaxf(v, __shfl_xor_sync(0xffffffffu, v, o));
    if (lane == 0) red[wid] = v;
    __syncthreads();
    int nw = (blockDim.x + 31) >> 5;
    float r = (wid == 0 && lane < nw) ? red[lane] : -INFINITY;
    if (wid == 0) {
        #pragma unroll
        for (int o = 16; o; o >>= 1) r = fmaxf(r, __shfl_xor_sync(0xffffffffu, r, o));
        if (lane == 0) red[0] = r;
    }
    __syncthreads();
    r = red[0];
    __syncthreads();
    return r;
}

// ================= small kernels ===========================================
__global__ void rownorm_kernel(const float* __restrict__ prior, float* __restrict__ Rf) {
    __shared__ float red[32];
    int i = blockIdx.x, t = threadIdx.x;
    const float* row = prior + (size_t)i * NP;
    float s = 0.f;
    for (int j = t; j < NP; j += 256) s += row[j];
    s = blockReduceSum(s, red);
    float inv = 1.f / fmaxf(s, 1e-12f);
    float* orow = Rf + (size_t)i * NP;
    for (int j = t; j < NP; j += 256) orow[j] = row[j] * inv;
}

__global__ void pool_kernel(const float* __restrict__ Xa, float* __restrict__ pooled) {
    int i = blockIdx.x, c = threadIdx.x;  // 128 threads
    const float* base = Xa + (size_t)i * (NC * CC) + c;
    float s = 0.f;
    #pragma unroll
    for (int k = 0; k < NC; k++) s += base[k * CC];
    pooled[i * CC + c] = s * (1.f / NC);
}

__global__ void pool_bf16_kernel(const __nv_bfloat16* __restrict__ H,
                                 const __nv_bfloat16* __restrict__ L,
                                 float* __restrict__ pooled) {
    int i = blockIdx.x, c = threadIdx.x;  // 128 threads
    size_t base = (size_t)i * (NC * CC) + c;
    float s = 0.f;
    #pragma unroll
    for (int k = 0; k < NC; k++)
        s += __bfloat162float(H[base + k * CC]) + __bfloat162float(L[base + k * CC]);
    pooled[i * CC + c] = s * (1.f / NC);
}

// W21 = W2 @ W1  : (64 x 128), K=64
__global__ void w21_kernel(const float* __restrict__ W2, const float* __restrict__ W1,
                           float* __restrict__ W21) {
    int idx = blockIdx.x * 256 + threadIdx.x;
    int d = idx >> 7, c = idx & 127;
    float s = 0.f;
    for (int e = 0; e < DD; e++) s += W2[d * DD + e] * W1[e * CC + c];
    W21[idx] = s;
}

// transpose + hi/lo split of delta weights: WT[m][c][d] from W[m][d][c]
__global__ void wt_kernel(const float* __restrict__ pfw, const float* __restrict__ adw,
                          __nv_bfloat16* __restrict__ WTH, __nv_bfloat16* __restrict__ WTL) {
    int c = blockIdx.x, m = blockIdx.y, d = threadIdx.x;
    const float* W = (m & 1) ? adw : pfw;
    W += (m >> 1) * CC * CC;
    float v = W[d * CC + c];
    __nv_bfloat16 h = __float2bfloat16_rn(v);
    WTH[(size_t)m * CC * CC + c * CC + d] = h;
    WTL[(size_t)m * CC * CC + c * CC + d] = __float2bfloat16_rn(v - __bfloat162float(h));
}

// t = pooled @ W21^T ; e3 = pooled @ W3^T   (2048 x 64, K=128)
__global__ void __launch_bounds__(256) proj_kernel(const float* __restrict__ pooled,
                                                   const float* __restrict__ W21,
                                                   const float* __restrict__ W3,
                                                   float* __restrict__ t_out,
                                                   float* __restrict__ e3_out) {
    __shared__ float sp[16][CC];
    int row0 = blockIdx.x * 16;
    int tid = threadIdx.x;
    for (int i = tid; i < 16 * CC; i += 256)
        sp[i >> 7][i & 127] = pooled[(size_t)(row0 + (i >> 7)) * CC + (i & 127)];
    __syncthreads();
    int n = tid & 63, rq = tid >> 6;
    float at[4] = {0, 0, 0, 0}, ae[4] = {0, 0, 0, 0};
    for (int c = 0; c < CC; c++) {
        float w21 = __ldg(&W21[n * CC + c]);
        float w3  = __ldg(&W3[n * CC + c]);
        #pragma unroll
        for (int j = 0; j < 4; j++) {
            float p = sp[rq + 4 * j][c];
            at[j] = fmaf(p, w21, at[j]);
            ae[j] = fmaf(p, w3, ae[j]);
        }
    }
    #pragma unroll
    for (int j = 0; j < 4; j++) {
        int r = row0 + rq + 4 * j;
        t_out[r * DD + n] = at[j];
        e3_out[r * DD + n] = ae[j];
    }
}

// fp32 -> (hi, lo) bf16, same layout
__global__ void conv_kernel(const float* __restrict__ A,
                            __nv_bfloat16* __restrict__ H, __nv_bfloat16* __restrict__ L) {
    size_t i = (size_t)(blockIdx.x * 256 + threadIdx.x) * 4;
    float4 v = *(const float4*)(A + i);
    __nv_bfloat16 h0 = __float2bfloat16_rn(v.x), h1 = __float2bfloat16_rn(v.y);
    __nv_bfloat16 h2 = __float2bfloat16_rn(v.z), h3 = __float2bfloat16_rn(v.w);
    __nv_bfloat162 hh0; hh0.x = h0; hh0.y = h1;
    __nv_bfloat162 hh1; hh1.x = h2; hh1.y = h3;
    __nv_bfloat162 ll0, ll1;
    ll0.x = __float2bfloat16_rn(v.x - __bfloat162float(h0));
    ll0.y = __float2bfloat16_rn(v.y - __bfloat162float(h1));
    ll1.x = __float2bfloat16_rn(v.z - __bfloat162float(h2));
    ll1.y = __float2bfloat16_rn(v.w - __bfloat162float(h3));
    *(__nv_bfloat162*)(H + i) = hh0; *(__nv_bfloat162*)(H + i + 2) = hh1;
    *(__nv_bfloat162*)(L + i) = ll0; *(__nv_bfloat162*)(L + i + 2) = ll1;
}

// ================= split-bf16 HMMA GEMM (big, 128x256 tile, z=2) ===========
// C[2048 x 8192] = A[2048 x 2048] @ B[2048 x 8192]; A,B hi/lo bf16 row-major.
// blockIdx.z selects (Rf path) vs (attn path). Output = hi/lo bf16 pair.
// smem per buffer (96KB): Ah@0 (16K) Al@16K Bh@32K (32K) Bl@64K (32K)
#define BUF_BYTES 98304
#define GEMM_SMEM (2 * BUF_BYTES)

__global__ void __launch_bounds__(256, 1) mma_gemm2(
    const __nv_bfloat16* __restrict__ AhF, const __nv_bfloat16* __restrict__ AlF,
    const __nv_bfloat16* __restrict__ BhF, const __nv_bfloat16* __restrict__ BlF,
    __nv_bfloat16* __restrict__ CfH, __nv_bfloat16* __restrict__ CfL,
    const __nv_bfloat16* __restrict__ AhA, const __nv_bfloat16* __restrict__ AlA,
    const __nv_bfloat16* __restrict__ BhA, const __nv_bfloat16* __restrict__ BlA,
    __nv_bfloat16* __restrict__ CaH, __nv_bfloat16* __restrict__ CaL) {
    extern __shared__ char smem[];
    uint32_t sbase = smem_to_u32(smem);
    int tid = threadIdx.x, wid = tid >> 5, lane = tid & 31;
    int bm = blockIdx.y * 128, bn = blockIdx.x * 256;
    int wm = (wid >> 2) * 64;   // 2 warp-rows
    int wn = (wid & 3) * 64;    // 4 warp-cols

    const __nv_bfloat16 *Ah, *Al, *Bh, *Bl;
    __nv_bfloat16 *CH, *CL;
    if (blockIdx.z == 0) { Ah = AhF; Al = AlF; Bh = BhF; Bl = BlF; CH = CfH; CL = CfL; }
    else                 { Ah = AhA; Al = AlA; Bh = BhA; Bl = BlA; CH = CaH; CL = CaL; }

    float acc[4][8][4];
    #pragma unroll
    for (int i = 0; i < 4; i++)
        #pragma unroll
        for (int j = 0; j < 8; j++)
            #pragma unroll
            for (int q = 0; q < 4; q++) acc[i][j][q] = 0.f;

    const int NCHUNK = NP / 64;   // 32

    auto load_chunk = [&](int ch, int buf) {
        int k0 = ch * 64;
        uint32_t s = sbase + buf * BUF_BYTES;
        // A hi/lo: 128 rows x 8 x 16B
        #pragma unroll
        for (int t = 0; t < 4; t++) {
            int i = tid + t * 256;
            int r = i >> 3, c = i & 7;
            uint32_t off = r * 128 + c * 16;
            uint32_t sw = off ^ (((off >> 7) & 7) << 4);
            const char* gh = (const char*)(Ah + (size_t)(bm + r) * NP + k0) + c * 16;
            const char* gl = (const char*)(Al + (size_t)(bm + r) * NP + k0) + c * 16;
            cp16(s + sw, gh);
            cp16(s + 16384 + sw, gl);
        }
        // B hi/lo: 64 k-rows x 32 x 16B (512B rows)
        #pragma unroll
        for (int t = 0; t < 8; t++) {
            int i = tid + t * 256;
            int k = i >> 5, n = i & 31;
            uint32_t off = k * 512 + n * 16;
            uint32_t sw = off ^ (((off >> 9) & 7) << 4);
            const char* gh = (const char*)(Bh + (size_t)(k0 + k) * NOUT + bn) + n * 16;
            const char* gl = (const char*)(Bl + (size_t)(k0 + k) * NOUT + bn) + n * 16;
            cp16(s + 32768 + sw, gh);
            cp16(s + 65536 + sw, gl);
        }
        asm volatile("cp.async.commit_group;" ::: "memory");
    };

    load_chunk(0, 0);

    for (int ch = 0; ch < NCHUNK; ch++) {
        if (ch + 1 < NCHUNK) load_chunk(ch + 1, (ch + 1) & 1);
        if (ch + 1 < NCHUNK) asm volatile("cp.async.wait_group 1;" ::: "memory");
        else                 asm volatile("cp.async.wait_group 0;" ::: "memory");
        __syncthreads();

        uint32_t s = sbase + (ch & 1) * BUF_BYTES;
        uint32_t sAh = s, sAl = s + 16384, sBh = s + 32768, sBl = s + 65536;

        #pragma unroll
        for (int kk = 0; kk < 64; kk += 16) {
            uint32_t ah[4][4], al[4][4];
            #pragma unroll
            for (int p = 0; p < 4; p++) {
                uint32_t off = (uint32_t)(wm + 16 * p + (lane & 15)) * 128
                             + kk * 2 + (lane >> 4) * 16;
                uint32_t sw = off ^ (((off >> 7) & 7) << 4);
                ldsm_x4(ah[p], sAh + sw);
                ldsm_x4(al[p], sAl + sw);
            }
            #pragma unroll
            for (int p = 0; p < 4; p++) {
                uint32_t off = (uint32_t)(kk + (lane & 15)) * 512
                             + (wn + p * 16) * 2 + (lane >> 4) * 16;
                uint32_t sw = off ^ (((off >> 9) & 7) << 4);
                uint32_t bh[4], bl[4];
                ldsm_x4_t(bh, sBh + sw);
                ldsm_x4_t(bl, sBl + sw);
                #pragma unroll
                for (int i = 0; i < 4; i++) {
                    mma_bf16(acc[i][2 * p],     ah[i], bh[0], bh[1]);
                    mma_bf16(acc[i][2 * p + 1], ah[i], bh[2], bh[3]);
                    mma_bf16(acc[i][2 * p],     al[i], bh[0], bh[1]);
                    mma_bf16(acc[i][2 * p + 1], al[i], bh[2], bh[3]);
                    mma_bf16(acc[i][2 * p],     ah[i], bl[0], bl[1]);
                    mma_bf16(acc[i][2 * p + 1], ah[i], bl[2], bl[3]);
                }
            }
        }
        __syncthreads();
    }

    // epilogue: split fp32 acc into hi/lo bf16
    int grp = lane >> 2, tig = lane & 3;
    #pragma unroll
    for (int i = 0; i < 4; i++)
        #pragma unroll
        for (int j = 0; j < 8; j++) {
            int row = bm + wm + 16 * i + grp;
            int col = bn + wn + 8 * j + 2 * tig;
            #pragma unroll
            for (int half = 0; half < 2; half++) {
                float a0 = acc[i][j][half * 2], a1 = acc[i][j][half * 2 + 1];
                __nv_bfloat16 h0 = __float2bfloat16_rn(a0);
                __nv_bfloat16 h1 = __float2bfloat16_rn(a1);
                __nv_bfloat162 hh; hh.x = h0; hh.y = h1;
                __nv_bfloat162 ll;
                ll.x = __float2bfloat16_rn(a0 - __bfloat162float(h0));
                ll.y = __float2bfloat16_rn(a1 - __bfloat162float(h1));
                size_t o = (size_t)(row + half * 8) * NOUT + col;
                *(__nv_bfloat162*)(CH + o) = hh;
                *(__nv_bfloat162*)(CL + o) = ll;
            }
        }
}

// ================= fused delta HMMA: res (+)= Xf@pfw^T + Xa@adw^T ==========
#define DELTA_SMEM (8 * 16384)

__global__ void __launch_bounds__(256, 1) delta_gemm(
    const __nv_bfloat16* __restrict__ XfH, const __nv_bfloat16* __restrict__ XfL,
    const __nv_bfloat16* __restrict__ XaH, const __nv_bfloat16* __restrict__ XaL,
    const __nv_bfloat16* __restrict__ WpH, const __nv_bfloat16* __restrict__ WpL,
    const __nv_bfloat16* __restrict__ WaH, const __nv_bfloat16* __restrict__ WaL,
    float* __restrict__ res, int accumulate) {
    extern __shared__ char smem[];
    uint32_t sbase = smem_to_u32(smem);
    int tid = threadIdx.x, wid = tid >> 5, lane = tid & 31;
    int bm = blockIdx.x * 128;
    int wm = (wid >> 1) * 32;
    int wn = (wid & 1) * 64;

    float acc[2][8][4];
    #pragma unroll
    for (int i = 0; i < 2; i++)
        #pragma unroll
        for (int j = 0; j < 8; j++)
            #pragma unroll
            for (int q = 0; q < 4; q++) acc[i][j][q] = 0.f;

    for (int cb = 0; cb < 2; cb++) {
        int c0 = cb * 64;
        #pragma unroll
        for (int t = 0; t < 4; t++) {
            int i = tid + t * 256;
            int r = i >> 3, c = i & 7;
            uint32_t off = r * 128 + c * 16;
            uint32_t sw = off ^ (((off >> 7) & 7) << 4);
            const char* p0 = (const char*)(XfH + (size_t)(bm + r) * CC + c0) + c * 16;
            const char* p1 = (const char*)(XfL + (size_t)(bm + r) * CC + c0) + c * 16;
            const char* p2 = (const char*)(XaH + (size_t)(bm + r) * CC + c0) + c * 16;
            const char* p3 = (const char*)(XaL + (size_t)(bm + r) * CC + c0) + c * 16;
            cp16(sbase + sw, p0);
            cp16(sbase + 16384 + sw, p1);
            cp16(sbase + 32768 + sw, p2);
            cp16(sbase + 49152 + sw, p3);
        }
        #pragma unroll
        for (int t = 0; t < 4; t++) {
            int i = tid + t * 256;
            int k = i >> 4, n = i & 15;
            uint32_t off = k * 256 + n * 16;
            uint32_t sw = off ^ (((off >> 8) & 7) << 4);
            const char* p0 = (const char*)(WpH + (size_t)(c0 + k) * CC) + n * 16;
            const char* p1 = (const char*)(WpL + (size_t)(c0 + k) * CC) + n * 16;
            const char* p2 = (const char*)(WaH + (size_t)(c0 + k) * CC) + n * 16;
            const char* p3 = (const char*)(WaL + (size_t)(c0 + k) * CC) + n * 16;
            cp16(sbase + 65536 + sw, p0);
            cp16(sbase + 81920 + sw, p1);
            cp16(sbase + 98304 + sw, p2);
            cp16(sbase + 114688 + sw, p3);
        }
        asm volatile("cp.async.commit_group;" ::: "memory");
        asm volatile("cp.async.wait_group 0;" ::: "memory");
        __syncthreads();

        #pragma unroll
        for (int kk = 0; kk < 64; kk += 16) {
            {
                uint32_t ah[2][4], al[2][4], bh[4][4], bl[4][4];
                #pragma unroll
                for (int p = 0; p < 2; p++) {
                    uint32_t off = (uint32_t)(wm + 16 * p + (lane & 15)) * 128
                                 + kk * 2 + (lane >> 4) * 16;
                    uint32_t sw = off ^ (((off >> 7) & 7) << 4);
                    ldsm_x4(ah[p], sbase + sw);
                    ldsm_x4(al[p], sbase + 16384 + sw);
                }
                #pragma unroll
                for (int p = 0; p < 4; p++) {
                    uint32_t off = (uint32_t)(kk + (lane & 15)) * 256
                                 + (wn + p * 16) * 2 + (lane >> 4) * 16;
                    uint32_t sw = off ^ (((off >> 8) & 7) << 4);
                    ldsm_x4_t(bh[p], sbase + 65536 + sw);
                    ldsm_x4_t(bl[p], sbase + 81920 + sw);
                }
                #pragma unroll
                for (int i = 0; i < 2; i++)
                    #pragma unroll
                    for (int j = 0; j < 8; j++) {
                        mma_bf16(acc[i][j], ah[i], bh[j >> 1][(j & 1) * 2], bh[j >> 1][(j & 1) * 2 + 1]);
                        mma_bf16(acc[i][j], al[i], bh[j >> 1][(j & 1) * 2], bh[j >> 1][(j & 1) * 2 + 1]);
                        mma_bf16(acc[i][j], ah[i], bl[j >> 1][(j & 1) * 2], bl[j >> 1][(j & 1) * 2 + 1]);
                    }
            }
            {
                uint32_t ah[2][4], al[2][4], bh[4][4], bl[4][4];
                #pragma unroll
                for (int p = 0; p < 2; p++) {
                    uint32_t off = (uint32_t)(wm + 16 * p + (lane & 15)) * 128
                                 + kk * 2 + (lane >> 4) * 16;
                    uint32_t sw = off ^ (((off >> 7) & 7) << 4);
                    ldsm_x4(ah[p], sbase + 32768 + sw);
                    ldsm_x4(al[p], sbase + 49152 + sw);
                }
                #pragma unroll
                for (int p = 0; p < 4; p++) {
                    uint32_t off = (uint32_t)(kk + (lane & 15)) * 256
                                 + (wn + p * 16) * 2 + (lane >> 4) * 16;
                    uint32_t sw = off ^ (((off >> 8) & 7) << 4);
                    ldsm_x4_t(bh[p], sbase + 98304 + sw);
                    ldsm_x4_t(bl[p], sbase + 114688 + sw);
                }
                #pragma unroll
                for (int i = 0; i < 2; i++)
                    #pragma unroll
                    for (int j = 0; j < 8; j++) {
                        mma_bf16(acc[i][j], ah[i], bh[j >> 1][(j & 1) * 2], bh[j >> 1][(j & 1) * 2 + 1]);
                        mma_bf16(acc[i][j], al[i], bh[j >> 1][(j & 1) * 2], bh[j >> 1][(j & 1) * 2 + 1]);
                        mma_bf16(acc[i][j], ah[i], bl[j >> 1][(j & 1) * 2], bl[j >> 1][(j & 1) * 2 + 1]);
                    }
            }
        }
        __syncthreads();
    }

    int grp = lane >> 2, tig = lane & 3;
    #pragma unroll
    for (int i = 0; i < 2; i++)
        #pragma unroll
        for (int j = 0; j < 8; j++) {
            int row = bm + wm + 16 * i + grp;
            int col = wn + 8 * j + 2 * tig;
            float* d0 = res + (size_t)row * CC + col;
            float* d1 = res + (size_t)(row + 8) * CC + col;
            if (accumulate) {
                float2 c0 = *(float2*)d0, c1 = *(float2*)d1;
                *(float2*)d0 = make_float2(c0.x + acc[i][j][0], c0.y + acc[i][j][1]);
                *(float2*)d1 = make_float2(c1.x + acc[i][j][2], c1.y + acc[i][j][3]);
            } else {
                *(float2*)d0 = make_float2(acc[i][j][0], acc[i][j][1]);
                *(float2*)d1 = make_float2(acc[i][j][2], acc[i][j][3]);
            }
        }
}

// ================= fp32 tiled NT (logits only) =============================
__global__ void __launch_bounds__(256) sgemm_nt(const float* __restrict__ A,
                                                const float* __restrict__ B,
                                                float* __restrict__ C,
                                                int M, int N, int K) {
    __shared__ __align__(16) float As[8][128];
    __shared__ __align__(16) float Bs[8][128];
    int tid = threadIdx.x;
    int bm = blockIdx.y * 128, bn = blockIdx.x * 128;
    int tr = (tid >> 4) << 3;
    int tc = (tid & 15) << 3;
    int aRow = tid >> 1, aCol = (tid & 1) << 2;
    int bN = tid >> 1, bK = (tid & 1) << 2;
    const float* Ap = A + (size_t)(bm + aRow) * K + aCol;
    const float* Bp = B + (size_t)(bn + bN) * K + bK;
    float acc[8][8];
    #pragma unroll
    for (int i = 0; i < 8; i++)
        #pragma unroll
        for (int j = 0; j < 8; j++) acc[i][j] = 0.f;
    for (int k0 = 0; k0 < K; k0 += 8) {
        float4 av = *(const float4*)(Ap + k0);
        As[aCol + 0][aRow] = av.x; As[aCol + 1][aRow] = av.y;
        As[aCol + 2][aRow] = av.z; As[aCol + 3][aRow] = av.w;
        float4 bv = *(const float4*)(Bp + k0);
        Bs[bK + 0][bN] = bv.x; Bs[bK + 1][bN] = bv.y;
        Bs[bK + 2][bN] = bv.z; Bs[bK + 3][bN] = bv.w;
        __syncthreads();
        #pragma unroll
        for (int kk = 0; kk < 8; kk++) {
            float4 a0 = *(const float4*)&As[kk][tr];
            float4 a1 = *(const float4*)&As[kk][tr + 4];
            float4 b0 = *(const float4*)&Bs[kk][tc];
            float4 b1 = *(const float4*)&Bs[kk][tc + 4];
            float ar[8] = {a0.x, a0.y, a0.z, a0.w, a1.x, a1.y, a1.z, a1.w};
            float br[8] = {b0.x, b0.y, b0.z, b0.w, b1.x, b1.y, b1.z, b1.w};
            #pragma unroll
            for (int i = 0; i < 8; i++)
                #pragma unroll
                for (int j = 0; j < 8; j++) acc[i][j] = fmaf(ar[i], br[j], acc[i][j]);
        }
        __syncthreads();
    }
    #pragma unroll
    for (int i = 0; i < 8; i++) {
        float* crow = C + (size_t)(bm + tr + i) * N + bn + tc;
        *(float4*)(crow)     = make_float4(acc[i][0], acc[i][1], acc[i][2], acc[i][3]);
        *(float4*)(crow + 4) = make_float4(acc[i][4], acc[i][5], acc[i][6], acc[i][7]);
    }
}

// ================= softmax + top-p via threshold bisection =================
__global__ void __launch_bounds__(512) topp_kernel(const float* __restrict__ logits,
                                                   __nv_bfloat16* __restrict__ H,
                                                   __nv_bfloat16* __restrict__ L) {
    const float P = 0.9f;
    __shared__ float red[32];
    int t = threadIdx.x;
    const float* row = logits + (size_t)blockIdx.x * NP;

    float v[4], mx = -INFINITY;
    #pragma unroll
    for (int e = 0; e < 4; e++) { v[e] = row[t + e * 512]; mx = fmaxf(mx, v[e]); }
    mx = blockReduceMax(mx, red);
    float z = 0.f;
    #pragma unroll
    for (int e = 0; e < 4; e++) { v[e] = expf(v[e] - mx); z += v[e]; }
    z = blockReduceSum(z, red);
    float invZ = 1.f / z;
    #pragma unroll
    for (int e = 0; e < 4; e++) v[e] *= invZ;

    float lo = 0.f, hi = invZ * 1.000001f + 1e-37f;
    for (int it = 0; it < 54; it++) {
        float mid = 0.5f * (lo + hi);
        float p = 0.f;
        #pragma unroll
        for (int e = 0; e < 4; e++) if (v[e] >= mid) p += v[e];
        p = blockReduceSum(p, red);
        if (p >= P) lo = mid; else hi = mid;
    }
    float cand = -INFINITY;
    #pragma unroll
    for (int e = 0; e < 4; e++) if (v[e] < hi) cand = fmaxf(cand, v[e]);
    float thr = blockReduceMax(cand, red);

    float msum = 0.f, mv[4];
    #pragma unroll
    for (int e = 0; e < 4; e++) {
        mv[e] = (v[e] >= thr) ? v[e] : 0.f;
        msum += mv[e];
    }
    msum = blockReduceSum(msum, red);
    float inv = 1.f / fmaxf(msum, 1e-12f);
    size_t base = (size_t)blockIdx.x * NP;
    #pragma unroll
    for (int e = 0; e < 4; e++) {
        float o = mv[e] * inv;
        __nv_bfloat16 h = __float2bfloat16_rn(o);
        H[base + t + e * 512] = h;
        L[base + t + e * 512] = __float2bfloat16_rn(o - __bfloat162float(h));
    }
}

// ================= gate + residual + layernorm =============================
__global__ void __launch_bounds__(128) ln_kernel(const float* __restrict__ x,
                                                 const float* __restrict__ res,
                                                 const float* __restrict__ gamma,
                                                 const float* __restrict__ beta,
                                                 const float* __restrict__ alpha,
                                                 float* __restrict__ out) {
    __shared__ float red[32];
    int row = blockIdx.x, c = threadIdx.x;
    float gate = 1.f / (1.f + expf(-alpha[0]));
    size_t idx = (size_t)row * CC + c;
    float h = x[idx] + gate * res[idx];
    float mu = blockReduceSum(h, red) * (1.f / CC);
    float d = h - mu;
    float var = blockReduceSum(d * d, red) * (1.f / CC);
    out[idx] = d * rsqrtf(var + 1e-5f) * gamma[c] + beta[c];
}

// ================= launch ==================================================
extern "C" void kernel_launch(void* const* d_in, const int* in_sizes, int n_in,
                              void* d_out, int out_size) {
    const float* x     = (const float*)d_in[0];
    const float* prior = (const float*)d_in[1];
    const float* W1    = (const float*)d_in[2];
    const float* W2    = (const float*)d_in[3];
    const float* W3    = (const float*)d_in[4];
    const float* pfw   = (const float*)d_in[5];
    const float* adw   = (const float*)d_in[6];
    const float* gamma = (const float*)d_in[7];
    const float* beta  = (const float*)d_in[8];
    const float* alpha = (const float*)d_in[9];
    float* out = (float*)d_out;

    float *Rf, *attn, *res, *pooled, *e3, *tt, *W21;
    __nv_bfloat16 *RfH, *RfL, *AtH, *AtL, *xH, *xL, *XfH, *XfL, *XaH, *XaL, *WTH, *WTL;
    cudaGetSymbolAddress((void**)&Rf, g_Rf);
    cudaGetSymbolAddress((void**)&attn, g_attn);
    cudaGetSymbolAddress((void**)&res, g_res);
    cudaGetSymbolAddress((void**)&pooled, g_pooled);
    cudaGetSymbolAddress((void**)&e3, g_e3);
    cudaGetSymbolAddress((void**)&tt, g_t);
    cudaGetSymbolAddress((void**)&W21, g_W21);
    cudaGetSymbolAddress((void**)&RfH, g_RfH);
    cudaGetSymbolAddress((void**)&RfL, g_RfL);
    cudaGetSymbolAddress((void**)&AtH, g_AtH);
    cudaGetSymbolAddress((void**)&AtL, g_AtL);
    cudaGetSymbolAddress((void**)&xH, g_xH);
    cudaGetSymbolAddress((void**)&xL, g_xL);
    cudaGetSymbolAddress((void**)&XfH, g_XfH);
    cudaGetSymbolAddress((void**)&XfL, g_XfL);
    cudaGetSymbolAddress((void**)&XaH, g_XaH);
    cudaGetSymbolAddress((void**)&XaL, g_XaL);
    cudaGetSymbolAddress((void**)&WTH, g_WTH);
    cudaGetSymbolAddress((void**)&WTL, g_WTL);

    cudaFuncSetAttribute(mma_gemm2, cudaFuncAttributeMaxDynamicSharedMemorySize, GEMM_SMEM);
    cudaFuncSetAttribute(delta_gemm, cudaFuncAttributeMaxDynamicSharedMemorySize, DELTA_SMEM);

    rownorm_kernel<<<NP, 256>>>(prior, Rf);
    conv_kernel<<<(NP * NP) / 1024, 256>>>(Rf, RfH, RfL);
    conv_kernel<<<XTOT / 1024, 256>>>(x, xH, xL);
    w21_kernel<<<32, 256>>>(W2, W1, W21);
    wt_kernel<<<dim3(CC, 4), CC>>>(pfw, adw, WTH, WTL);

    for (int step = 0; step < 2; step++) {
        if (step == 0)
            pool_kernel<<<NP, 128>>>(x, pooled);
        else
            pool_bf16_kernel<<<NP, 128>>>(XaH, XaL, pooled);

        proj_kernel<<<NP / 16, 256>>>(pooled, W21, W3, tt, e3);
        sgemm_nt<<<dim3(NP / 128, NP / 128), 256>>>(tt, e3, attn, NP, NP, DD);
        topp_kernel<<<NP, 512>>>(attn, AtH, AtL);

        const __nv_bfloat16* BfH = (step == 0) ? xH : XfH;
        const __nv_bfloat16* BfL = (step == 0) ? xL : XfL;
        const __nv_bfloat16* BaH = (step == 0) ? xH : XaH;
        const __nv_bfloat16* BaL = (step == 0) ? xL : XaL;
        __nv_bfloat16* OfH = XfH + (size_t)step * XTOT;
        __nv_bfloat16* OfL = XfL + (size_t)step * XTOT;
        __nv_bfloat16* OaH = XaH + (size_t)step * XTOT;
        __nv_bfloat16* OaL = XaL + (size_t)step * XTOT;

        mma_gemm2<<<dim3(NOUT / 256, NP / 128, 2), 256, GEMM_SMEM>>>(
            RfH, RfL, BfH, BfL, OfH, OfL,
            AtH, AtL, BaH, BaL, OaH, OaL);

        const __nv_bfloat16* wp_h = WTH + (size_t)(2 * step + 0) * CC * CC;
        const __nv_bfloat16* wp_l = WTL + (size_t)(2 * step + 0) * CC * CC;
        const __nv_bfloat16* wa_h = WTH + (size_t)(2 * step + 1) * CC * CC;
        const __nv_bfloat16* wa_l = WTL + (size_t)(2 * step + 1) * CC * CC;
        delta_gemm<<<(NP * NC) / 128, 256, DELTA_SMEM>>>(
            OfH, OfL, OaH, OaL, wp_h, wp_l, wa_h, wa_l, res, step);
    }

    ln_kernel<<<NP * NC, 128>>>(x, res, gamma, beta, alpha, out);
}